// round 11
// baseline (speedup 1.0000x reference)
#include <cuda_runtime.h>
#include <math.h>

#define B_ 2
#define S_ 2048
#define C_ 1536
#define HQ_ 16
#define HKV_ 4
#define DQK_ 128
#define DV_ 96
#define EPSF 1e-5f
#define NQKV 2944   // 2048 + 512 + 384

// ---------------- scratch ----------------
__device__ float g_h[B_*S_*C_];
__device__ float g_q[B_*S_*HQ_*DQK_];
__device__ float g_k[B_*S_*HKV_*DQK_];
__device__ float g_v[B_*S_*HKV_*DV_];
__device__ float g_vt[B_*HKV_*DV_*S_];  // V transposed [b][kv][dv][s]
__device__ float g_y[B_*S_*HQ_*DV_];
__device__ float g_wqkv[NQKV*C_];       // tf32 Wq|Wk|Wv, TRANSPOSED [N][K]
__device__ float g_wo[C_*C_];           // tf32 Wo, TRANSPOSED [N][K]
__device__ float g_invf[64];            // RoPE inverse frequencies

// ---------------- helpers ----------------
__device__ __forceinline__ unsigned f2tf(float f) {
    unsigned u;
    asm("cvt.rna.tf32.f32 %0, %1;" : "=r"(u) : "f"(f));
    return u;
}
__device__ __forceinline__ float f2tff(float f) { return __uint_as_float(f2tf(f)); }
__device__ __forceinline__ float ex2f(float x) {
    float r;
    asm("ex2.approx.ftz.f32 %0, %1;" : "=f"(r) : "f"(x));
    return r;
}
__device__ __forceinline__ float tanhaf(float x) {
    float r;
    asm("tanh.approx.f32 %0, %1;" : "=f"(r) : "f"(x));
    return r;
}
__device__ __forceinline__ void mma_tf32(float c[4], const unsigned a[4], const unsigned b[2]) {
    asm volatile(
        "mma.sync.aligned.m16n8k8.row.col.f32.tf32.tf32.f32 "
        "{%0,%1,%2,%3},{%4,%5,%6,%7},{%8,%9},{%0,%1,%2,%3};"
        : "+f"(c[0]), "+f"(c[1]), "+f"(c[2]), "+f"(c[3])
        : "r"(a[0]), "r"(a[1]), "r"(a[2]), "r"(a[3]), "r"(b[0]), "r"(b[1]));
}
#define LDSM4(d, addr) \
    asm volatile("ldmatrix.sync.aligned.m8n8.x4.shared.b16 {%0,%1,%2,%3}, [%4];" \
        : "=r"((d)[0]), "=r"((d)[1]), "=r"((d)[2]), "=r"((d)[3]) : "r"(addr))
__device__ __forceinline__ unsigned sm_u32(const void* p) {
    return (unsigned)__cvta_generic_to_shared(p);
}
__device__ __forceinline__ void cp16(void* smem, const void* gp) {
    unsigned s = sm_u32(smem);
    asm volatile("cp.async.cg.shared.global [%0], [%1], 16;\n" :: "r"(s), "l"(gp));
}
__device__ __forceinline__ void cp_commit() { asm volatile("cp.async.commit_group;\n"); }
__device__ __forceinline__ void cp_wait0() { asm volatile("cp.async.wait_group 0;\n"); }
__device__ __forceinline__ void cp_wait1() { asm volatile("cp.async.wait_group 1;\n"); }

// ---------------- 0a. RoPE table ----------------
__global__ void rope_table_kernel() {
    int i = threadIdx.x;
    double lg63 = log(1985.0) / 63.0;
    double geom = exp((double)i * lg63);
    g_invf[i] = (float)(1.0 / ((double)i + geom));
}

// ---------------- 0b. tiled transpose + tf32 round ----------------
__global__ void transpose_tf32(const float* __restrict__ src, float* __restrict__ dst,
                               int R, int Cc) {
    __shared__ float tile[32][33];
    int x = blockIdx.x*32 + threadIdx.x;
    int y0 = blockIdx.y*32;
    #pragma unroll
    for (int j = threadIdx.y; j < 32; j += 8)
        tile[j][threadIdx.x] = src[(size_t)(y0+j)*Cc + x];
    __syncthreads();
    int xo = blockIdx.y*32 + threadIdx.x;
    int yo0 = blockIdx.x*32;
    #pragma unroll
    for (int j = threadIdx.y; j < 32; j += 8)
        dst[(size_t)(yo0+j)*R + xo] = f2tff(tile[threadIdx.x][j]);
}

// ---------------- 1. rms_bn1 ----------------
__global__ void rmsbn1_kernel(const float* __restrict__ x, const float* __restrict__ g,
                              const float* __restrict__ ms) {
    int idx = (blockIdx.x * blockDim.x + threadIdx.x) * 4;
    if (idx >= B_*S_*C_) return;
    float4 xv = *(const float4*)(x + idx);
    int c = idx % C_;
    float4 o;
    o.x = f2tff(xv.x * g[c+0] * rsqrtf(ms[c+0] + EPSF));
    o.y = f2tff(xv.y * g[c+1] * rsqrtf(ms[c+1] + EPSF));
    o.z = f2tff(xv.z * g[c+2] * rsqrtf(ms[c+2] + EPSF));
    o.w = f2tff(xv.w * g[c+3] * rsqrtf(ms[c+3] + EPSF));
    *(float4*)(g_h + idx) = o;
}

// ---------------- 2. tf32 GEMM 128x128x32 ----------------
#define AS_STR 36
#define BS_STR 36
#define AS_BUF (128*AS_STR)
#define BS_BUF (128*BS_STR)

template<int MODE>
__global__ void __launch_bounds__(256, 2) tf32gemm_kernel(
    const float* __restrict__ A, const float* __restrict__ Bt, float* __restrict__ Cm,
    int M, int N, int K,
    const float* __restrict__ bias, const float* __restrict__ bng,
    const float* __restrict__ bnms,
    float* __restrict__ gq, float* __restrict__ gk, float* __restrict__ gv)
{
    extern __shared__ float sm[];
    float* As = sm;
    float* Bs = sm + 2*AS_BUF;

    int tid = threadIdx.x;
    int lane = tid & 31, wid = tid >> 5;
    int wm = wid & 3, wn = wid >> 2;
    int g = lane >> 2, q = lane & 3;
    int bx = blockIdx.x, by = blockIdx.y;

    int t7 = lane & 7, qb0 = (lane >> 3) & 1, qb1 = (lane >> 4) & 1;
    unsigned aoff[2], boff[4];
    #pragma unroll
    for (int mt = 0; mt < 2; mt++)
        aoff[mt] = ((wm*32 + mt*16 + qb0*8 + t7)*AS_STR + qb1*4)*4;
    #pragma unroll
    for (int nt2 = 0; nt2 < 4; nt2++)
        boff[nt2] = ((wn*64 + nt2*16 + qb1*8 + t7)*BS_STR + qb0*4)*4;

    float acc[2][8][4];
    #pragma unroll
    for (int mt = 0; mt < 2; mt++)
        #pragma unroll
        for (int nt = 0; nt < 8; nt++)
            #pragma unroll
            for (int i = 0; i < 4; i++) acc[mt][nt][i] = 0.f;

    const int nk = K / 32;
    {
        #pragma unroll
        for (int i = 0; i < 4; i++) {
            int f4 = tid + i*256;
            int r = f4 >> 3, c = (f4 & 7) * 4;
            cp16(As + r*AS_STR + c, A + (size_t)(by*128 + r)*K + c);
            cp16(Bs + r*BS_STR + c, Bt + (size_t)(bx*128 + r)*K + c);
        }
        cp_commit();
    }

    for (int kt = 0; kt < nk; kt++) {
        cp_wait0();
        __syncthreads();
        if (kt + 1 < nk) {
            float* Ad = As + ((kt+1)&1)*AS_BUF;
            float* Bd = Bs + ((kt+1)&1)*BS_BUF;
            int k0 = (kt+1)*32;
            #pragma unroll
            for (int i = 0; i < 4; i++) {
                int f4 = tid + i*256;
                int r = f4 >> 3, c = (f4 & 7) * 4;
                cp16(Ad + r*AS_STR + c, A + (size_t)(by*128 + r)*K + k0 + c);
                cp16(Bd + r*BS_STR + c, Bt + (size_t)(bx*128 + r)*K + k0 + c);
            }
            cp_commit();
        }
        unsigned uA = sm_u32(As + (kt&1)*AS_BUF);
        unsigned uB = sm_u32(Bs + (kt&1)*BS_BUF);
        #pragma unroll
        for (int kk = 0; kk < 32; kk += 8) {
            unsigned a[2][4], b[4][4];
            LDSM4(a[0], uA + aoff[0] + kk*4);
            LDSM4(a[1], uA + aoff[1] + kk*4);
            #pragma unroll
            for (int nt2 = 0; nt2 < 4; nt2++) LDSM4(b[nt2], uB + boff[nt2] + kk*4);
            #pragma unroll
            for (int mt = 0; mt < 2; mt++)
                #pragma unroll
                for (int nt = 0; nt < 8; nt++)
                    mma_tf32(acc[mt][nt], a[mt], &b[nt>>1][(nt&1)*2]);
        }
    }

    #pragma unroll
    for (int mt = 0; mt < 2; mt++) {
        int row = by*128 + wm*32 + mt*16 + g;
        #pragma unroll
        for (int nt = 0; nt < 8; nt++) {
            int col = bx*128 + wn*64 + nt*8 + 2*q;
            float v0 = acc[mt][nt][0], v1 = acc[mt][nt][1];
            float v2 = acc[mt][nt][2], v3 = acc[mt][nt][3];
            if (MODE == 2) {
                float s0 = bng[col]   * rsqrtf(bnms[col]   + EPSF);
                float s1 = bng[col+1] * rsqrtf(bnms[col+1] + EPSF);
                v0 = (v0 + bias[col])   * s0;
                v1 = (v1 + bias[col+1]) * s1;
                v2 = (v2 + bias[col])   * s0;
                v3 = (v3 + bias[col+1]) * s1;
                *(float2*)(Cm + (size_t)row*N + col)     = make_float2(v0, v1);
                *(float2*)(Cm + (size_t)(row+8)*N + col) = make_float2(v2, v3);
            } else {
                float *d0, *d1;
                if (col < 2048) {
                    d0 = gq + (size_t)row*2048 + col;
                    d1 = gq + (size_t)(row+8)*2048 + col;
                } else if (col < 2560) {
                    d0 = gk + (size_t)row*512 + (col - 2048);
                    d1 = gk + (size_t)(row+8)*512 + (col - 2048);
                } else {
                    d0 = gv + (size_t)row*384 + (col - 2560);
                    d1 = gv + (size_t)(row+8)*384 + (col - 2560);
                }
                *(float2*)d0 = make_float2(v0, v1);
                *(float2*)d1 = make_float2(v2, v3);
            }
        }
    }
}

// ---------------- 3. per-head LayerNorm (+RoPE via table) ----------------
// OUT: 0 = in-place (k), 1 = in-place with Q-prescale, 2 = transposed V write
template<int D, bool ROPE, int H, int OUT>
__global__ void ln_head_kernel(float* __restrict__ data, const float* __restrict__ gg,
                               const float* __restrict__ bb, float* __restrict__ vt) {
    const int NV = D / 32;
    int gw = (blockIdx.x * blockDim.x + threadIdx.x) >> 5;
    int lane = threadIdx.x & 31;
    float* row = data + (size_t)gw * D;
    int s = (gw / H) % S_;
    int d0 = lane * NV;

    float vals[NV];
    #pragma unroll
    for (int i = 0; i < NV; i++) vals[i] = row[d0 + i];

    float sum = 0.f, sq = 0.f;
    #pragma unroll
    for (int i = 0; i < NV; i++) { sum += vals[i]; sq += vals[i]*vals[i]; }
    #pragma unroll
    for (int off = 16; off > 0; off >>= 1) {
        sum += __shfl_xor_sync(0xffffffffu, sum, off);
        sq  += __shfl_xor_sync(0xffffffffu, sq,  off);
    }
    float mean = sum * (1.0f / D);
    float var  = sq  * (1.0f / D) - mean * mean;
    float inv  = rsqrtf(var + EPSF);
    #pragma unroll
    for (int i = 0; i < NV; i++)
        vals[i] = (vals[i] - mean) * inv * gg[d0 + i] + bb[d0 + i];

    if (ROPE) {
        #pragma unroll
        for (int p = 0; p < NV/2; p++) {
            int fi = (d0 >> 1) + p;
            float invf = g_invf[fi];
            float theta = (float)s * invf;
            float sn, cs;
            sincosf(theta, &sn, &cs);
            float x0 = vals[2*p], x1 = vals[2*p + 1];
            vals[2*p]     = x0 * cs - x1 * sn;
            vals[2*p + 1] = x1 * cs + x0 * sn;
        }
    }
    if (OUT == 1) {
        // fold tanh-softmax front-end into Q: (1/sqrt(128)) * (1/5)
        const float QPRE = 0.2f * 0.08838834764831845f;
        #pragma unroll
        for (int i = 0; i < NV; i++) row[d0 + i] = f2tff(vals[i] * QPRE);
    } else if (OUT == 2) {
        int kv = gw % H;
        int b  = gw / (H * S_);
        float* base = vt + ((size_t)(b*H + kv)*D)*S_ + s;
        #pragma unroll
        for (int i = 0; i < NV; i++) base[(size_t)(d0 + i)*S_] = f2tff(vals[i]);
    } else {
        #pragma unroll
        for (int i = 0; i < NV; i++) row[d0 + i] = f2tff(vals[i]);
    }
}

// ---------------- 4. GQA flash: full kv-group per CTA, 512 thr, 3-stage pipe ----
// 128 rows (4 heads x 32 queries) x 32-key tiles; 16 warps (8m x 2n); warp owns
// 16 rows x 16 keys; partial O merged once at the end. K/V triple-buffered with
// cp.async wait_group 1 (loads get 2 tile-periods to land).
#define QS_STR 132
#define VT_STR 36
#define PS_STR 36
#define MG_STR 100
#define FQ_OFF 0
#define FK_OFF (128*QS_STR)             // 16896
#define FK_BUF (32*QS_STR)              // 4224
#define FV_OFF (FK_OFF + 3*FK_BUF)      // 29568
#define FV_BUF (96*VT_STR)              // 3456
#define FP_OFF (FV_OFF + 3*FV_BUF)      // 39936
#define FR_OFF (FP_OFF + 128*PS_STR)    // 44544
#define FLASH_SMEM ((FR_OFF + 384) * 4) // 179712 B

__global__ void __launch_bounds__(512, 1) flash_kernel() {
    extern __shared__ float sm[];
    float* Qs = sm + FQ_OFF;
    float* Ks = sm + FK_OFF;
    float* Vs = sm + FV_OFF;
    float* Ps = sm + FP_OFF;
    float* Red = sm + FR_OFF;

    int bx = blockIdx.x;                   // b*4 + kv
    int b  = bx >> 2;
    int kv = bx & 3;
    int s0 = blockIdx.y * 32;
    int tid = threadIdx.x;
    int lane = tid & 31, wid = tid >> 5;
    int wm = wid & 7, wn = wid >> 3;       // 8m x 2n: warp = 16 rows x 16 keys
    int g = lane >> 2, q = lane & 3;
    int t7 = lane & 7, qb0 = (lane >> 3) & 1, qb1 = (lane >> 4) & 1;

    unsigned qoff = ((wm*16 + qb0*8 + t7)*QS_STR + qb1*4)*4;
    unsigned koff = ((wn*16 + qb1*8 + t7)*QS_STR + qb0*4)*4;
    unsigned poff = ((wm*16 + qb0*8 + t7)*PS_STR + wn*16 + qb1*4)*4;
    unsigned voff[6];
    #pragma unroll
    for (int nt = 0; nt < 6; nt++)
        voff[nt] = ((nt*16 + qb1*8 + t7)*VT_STR + wn*16 + qb0*4)*4;
    unsigned uQ = sm_u32(Qs) + qoff;
    unsigned uP = sm_u32(Ps) + poff;

    float acc[12][4];                      // 16 rows x 96 dv partial (own keys)
    #pragma unroll
    for (int m = 0; m < 12; m++)
        #pragma unroll
        for (int i = 0; i < 4; i++) acc[m][i] = 0.f;
    float rs[2] = {0.f, 0.f};

    const float* kb0 = g_k + ((size_t)(b*S_)*HKV_ + kv)*DQK_;
    const float* vtb = g_vt + ((size_t)(b*HKV_ + kv)*DV_)*S_;

    // Q: 128 rows = head (r>>5), query r&31
    #pragma unroll
    for (int i = 0; i < 8; i++) {
        int f4 = tid + i*512;
        int r = f4 >> 5, c = (f4 & 31) * 4;
        int he = kv + (r >> 5)*HKV_;
        int qr = r & 31;
        cp16(Qs + r*QS_STR + c,
             g_q + ((size_t)((b*S_ + s0 + qr)*HQ_ + he))*DQK_ + c);
    }
    // prefetch K/V tiles 0 and 1 (separate commit groups)
    #pragma unroll
    for (int pf = 0; pf < 2; pf++) {
        float* kd = Ks + pf*FK_BUF;
        float* vd = Vs + pf*FV_BUF;
        #pragma unroll
        for (int i = 0; i < 2; i++) {
            int f4 = tid + i*512;
            int r = f4 >> 5, c = (f4 & 31) * 4;
            cp16(kd + r*QS_STR + c, kb0 + (size_t)(pf*32 + r)*HKV_*DQK_ + c);
        }
        #pragma unroll
        for (int i = 0; i < 2; i++) {
            int f4 = tid + i*512;
            if (f4 < 768) {
                int r = f4 >> 3, c = (f4 & 7) * 4;
                cp16(vd + r*VT_STR + c, vtb + (size_t)r*S_ + pf*32 + c);
            }
        }
        cp_commit();
    }

    int prow = wm*16 + g;

    for (int t0 = 0; t0 < 64; t0++) {
        cp_wait1();                        // tile t0 landed; t0+1 may be in flight
        __syncthreads();
        if (t0 + 2 < 64) {
            int tp = t0 + 2;
            float* kd = Ks + (tp % 3)*FK_BUF;
            float* vd = Vs + (tp % 3)*FV_BUF;
            #pragma unroll
            for (int i = 0; i < 2; i++) {
                int f4 = tid + i*512;
                int r = f4 >> 5, c = (f4 & 31) * 4;
                cp16(kd + r*QS_STR + c, kb0 + (size_t)(tp*32 + r)*HKV_*DQK_ + c);
            }
            #pragma unroll
            for (int i = 0; i < 2; i++) {
                int f4 = tid + i*512;
                if (f4 < 768) {
                    int r = f4 >> 3, c = (f4 & 7) * 4;
                    cp16(vd + r*VT_STR + c, vtb + (size_t)r*S_ + tp*32 + c);
                }
            }
            cp_commit();
        }
        unsigned uK = sm_u32(Ks + (t0 % 3)*FK_BUF) + koff;
        unsigned uV = sm_u32(Vs + (t0 % 3)*FV_BUF);

        // S = Q K^T (warp: 16 rows x own 16 keys); Q pre-scaled by scl/5
        float sacc[2][4];
        #pragma unroll
        for (int nt = 0; nt < 2; nt++)
            #pragma unroll
            for (int i = 0; i < 4; i++) sacc[nt][i] = 0.f;

        #pragma unroll
        for (int kk = 0; kk < DQK_; kk += 8) {
            unsigned aq[4], bk[4];
            LDSM4(aq, uQ + kk*4);
            LDSM4(bk, uK + kk*4);
            mma_tf32(sacc[0], aq, &bk[0]);
            mma_tf32(sacc[1], aq, &bk[2]);
        }

        // preload V fragments (kc0) — independent of softmax
        unsigned bv[6][4];
        #pragma unroll
        for (int nt = 0; nt < 6; nt++) LDSM4(bv[nt], uV + voff[nt]);

        // p = exp(5*tanh(l/5)) = 2^(7.2135 * tanh.approx(sacc))
        #pragma unroll
        for (int nt = 0; nt < 2; nt++) {
            #pragma unroll
            for (int ci = 0; ci < 4; ci++) {
                float t = tanhaf(sacc[nt][ci]);
                float p = ex2f(7.213475204444817f * t);
                float pr = f2tff(p);
                rs[ci >> 1] += pr;
                int row = prow + ((ci >= 2) ? 8 : 0);
                int col = wn*16 + nt*8 + 2*q + (ci & 1);
                Ps[row*PS_STR + col] = pr;
            }
        }
        __syncwarp();

        // acc += P_own @ V_own; kc1 V fragments loaded as kc0 ones retire
        unsigned ap0[4], ap1[4];
        LDSM4(ap0, uP);
        LDSM4(ap1, uP + 32);
        #pragma unroll
        for (int nt = 0; nt < 6; nt++) {
            mma_tf32(acc[2*nt],   ap0, &bv[nt][0]);
            mma_tf32(acc[2*nt+1], ap0, &bv[nt][2]);
            LDSM4(bv[nt], uV + voff[nt] + 32);
        }
        #pragma unroll
        for (int nt = 0; nt < 6; nt++) {
            mma_tf32(acc[2*nt],   ap1, &bv[nt][0]);
            mma_tf32(acc[2*nt+1], ap1, &bv[nt][2]);
        }
    }

    // row sums: reduce over q lanes; per-wn partials to Red
    #pragma unroll
    for (int i = 0; i < 2; i++) {
        rs[i] += __shfl_xor_sync(0xffffffffu, rs[i], 1);
        rs[i] += __shfl_xor_sync(0xffffffffu, rs[i], 2);
    }
    if (q == 0) {
        Red[prow*2 + wn]     = rs[0];
        Red[(prow+8)*2 + wn] = rs[1];
    }
    __syncthreads();                       // all compute done; K/V buffers dead

    // merge partial O across the 2 wn warps via smem (alias of K/V buffers)
    float* Mg = Ks;                        // [128][MG_STR] = 51.2KB <= K+V region
    if (wn == 1) {
        #pragma unroll
        for (int m = 0; m < 12; m++) {
            int dv = m*8 + 2*q;
            *(float2*)&Mg[prow*MG_STR + dv]     = make_float2(acc[m][0], acc[m][1]);
            *(float2*)&Mg[(prow+8)*MG_STR + dv] = make_float2(acc[m][2], acc[m][3]);
        }
    }
    __syncthreads();
    if (wn == 0) {
        float inv0 = 1.0f / (Red[prow*2] + Red[prow*2 + 1]);
        float inv1 = 1.0f / (Red[(prow+8)*2] + Red[(prow+8)*2 + 1]);
        int r0 = prow, r1 = prow + 8;      // same head (16-row groups)
        int he0 = kv + (r0 >> 5)*HKV_;
        int he1 = kv + (r1 >> 5)*HKV_;
        size_t base0 = ((size_t)((b*S_ + s0 + (r0 & 31))*HQ_ + he0))*DV_;
        size_t base1 = ((size_t)((b*S_ + s0 + (r1 & 31))*HQ_ + he1))*DV_;
        #pragma unroll
        for (int m = 0; m < 12; m++) {
            int dv = m*8 + 2*q;
            float2 o0 = *(float2*)&Mg[prow*MG_STR + dv];
            float2 o1 = *(float2*)&Mg[(prow+8)*MG_STR + dv];
            *(float2*)(g_y + base0 + dv) =
                make_float2(f2tff((acc[m][0] + o0.x)*inv0), f2tff((acc[m][1] + o0.y)*inv0));
            *(float2*)(g_y + base1 + dv) =
                make_float2(f2tff((acc[m][2] + o1.x)*inv1), f2tff((acc[m][3] + o1.y)*inv1));
        }
    }
}

// ---------------- launch ----------------
extern "C" void kernel_launch(void* const* d_in, const int* in_sizes, int n_in,
                              void* d_out, int out_size) {
    const float* x      = (const float*)d_in[0];
    const float* bn1_g  = (const float*)d_in[1];
    const float* bn1_ms = (const float*)d_in[2];
    const float* Wq     = (const float*)d_in[3];
    const float* Wk     = (const float*)d_in[4];
    const float* Wv     = (const float*)d_in[5];
    const float* qn_g   = (const float*)d_in[6];
    const float* qn_b   = (const float*)d_in[7];
    const float* kn_g   = (const float*)d_in[8];
    const float* kn_b   = (const float*)d_in[9];
    const float* vn_g   = (const float*)d_in[10];
    const float* vn_b   = (const float*)d_in[11];
    const float* Wo     = (const float*)d_in[12];
    const float* bo     = (const float*)d_in[13];
    const float* bn2_g  = (const float*)d_in[14];
    const float* bn2_ms = (const float*)d_in[15];
    float* out = (float*)d_out;

    float *ph, *pq, *pk, *pv, *pvt, *py, *pwqkv, *pwo;
    cudaGetSymbolAddress((void**)&ph, g_h);
    cudaGetSymbolAddress((void**)&pq, g_q);
    cudaGetSymbolAddress((void**)&pk, g_k);
    cudaGetSymbolAddress((void**)&pv, g_v);
    cudaGetSymbolAddress((void**)&pvt, g_vt);
    cudaGetSymbolAddress((void**)&py, g_y);
    cudaGetSymbolAddress((void**)&pwqkv, g_wqkv);
    cudaGetSymbolAddress((void**)&pwo, g_wo);

    const int M = B_ * S_;
    const int gemm_smem = (2*AS_BUF + 2*BS_BUF) * 4;

    cudaFuncSetAttribute(tf32gemm_kernel<1>, cudaFuncAttributeMaxDynamicSharedMemorySize, gemm_smem);
    cudaFuncSetAttribute(tf32gemm_kernel<2>, cudaFuncAttributeMaxDynamicSharedMemorySize, gemm_smem);
    cudaFuncSetAttribute(flash_kernel, cudaFuncAttributeMaxDynamicSharedMemorySize, FLASH_SMEM);

    // 0. RoPE table + weight transpose/tf32 conversion
    rope_table_kernel<<<1, 64>>>();
    {
        dim3 blk(32, 8);
        transpose_tf32<<<dim3(2048/32, C_/32), blk>>>(Wq, pwqkv,           C_, 2048);
        transpose_tf32<<<dim3(512/32,  C_/32), blk>>>(Wk, pwqkv + 2048*C_, C_, 512);
        transpose_tf32<<<dim3(384/32,  C_/32), blk>>>(Wv, pwqkv + 2560*C_, C_, 384);
        transpose_tf32<<<dim3(C_/32,   C_/32), blk>>>(Wo, pwo,             C_, C_);
    }

    // 1. rms_bn1
    rmsbn1_kernel<<<(B_*S_*C_/4 + 255)/256, 256>>>(x, bn1_g, bn1_ms);

    // 2. fused QKV projection
    tf32gemm_kernel<1><<<dim3(NQKV/128, M/128), 256, gemm_smem>>>(
        ph, pwqkv, nullptr, M, NQKV, C_, nullptr, nullptr, nullptr, pq, pk, pv);

    // 3. per-head LN (+RoPE); Q pre-scaled for tanh softmax; V transposed
    ln_head_kernel<DQK_, true,  HQ_,  1><<<(B_*S_*HQ_)/8,  256>>>(pq, qn_g, qn_b, nullptr);
    ln_head_kernel<DQK_, true,  HKV_, 0><<<(B_*S_*HKV_)/8, 256>>>(pk, kn_g, kn_b, nullptr);
    ln_head_kernel<DV_,  false, HKV_, 2><<<(B_*S_*HKV_)/8, 256>>>(pv, vn_g, vn_b, pvt);

    // 4. attention: full GQA group per CTA (K/V traffic halved), 3-stage pipeline
    flash_kernel<<<dim3(B_*HKV_, S_/32), 512, FLASH_SMEM>>>();

    // 5. output projection + bias + rms_bn2
    tf32gemm_kernel<2><<<dim3(C_/128, M/128), 256, gemm_smem>>>(
        py, pwo, out, M, C_, HQ_*DV_, bo, bn2_g, bn2_ms, nullptr, nullptr, nullptr);
}

// round 12
// speedup vs baseline: 1.0523x; 1.0523x over previous
#include <cuda_runtime.h>
#include <math.h>

#define B_ 2
#define S_ 2048
#define C_ 1536
#define HQ_ 16
#define HKV_ 4
#define DQK_ 128
#define DV_ 96
#define EPSF 1e-5f
#define NQKV 2944   // 2048 + 512 + 384

// ---------------- scratch ----------------
__device__ float g_h[B_*S_*C_];
__device__ float g_q[B_*S_*HQ_*DQK_];
__device__ float g_k[B_*S_*HKV_*DQK_];
__device__ float g_v[B_*S_*HKV_*DV_];
__device__ float g_vt[B_*HKV_*DV_*S_];  // V transposed [b][kv][dv][s]
__device__ float g_y[B_*S_*HQ_*DV_];
__device__ float g_wqkv[NQKV*C_];       // tf32 Wq|Wk|Wv, TRANSPOSED [N][K]
__device__ float g_wo[C_*C_];           // tf32 Wo, TRANSPOSED [N][K]
__device__ float g_invf[64];            // RoPE inverse frequencies

// ---------------- helpers ----------------
__device__ __forceinline__ unsigned f2tf(float f) {
    unsigned u;
    asm("cvt.rna.tf32.f32 %0, %1;" : "=r"(u) : "f"(f));
    return u;
}
__device__ __forceinline__ float f2tff(float f) { return __uint_as_float(f2tf(f)); }
__device__ __forceinline__ float ex2f(float x) {
    float r;
    asm("ex2.approx.ftz.f32 %0, %1;" : "=f"(r) : "f"(x));
    return r;
}
__device__ __forceinline__ float tanhaf(float x) {
    float r;
    asm("tanh.approx.f32 %0, %1;" : "=f"(r) : "f"(x));
    return r;
}
__device__ __forceinline__ void mma_tf32(float c[4], const unsigned a[4], const unsigned b[2]) {
    asm volatile(
        "mma.sync.aligned.m16n8k8.row.col.f32.tf32.tf32.f32 "
        "{%0,%1,%2,%3},{%4,%5,%6,%7},{%8,%9},{%0,%1,%2,%3};"
        : "+f"(c[0]), "+f"(c[1]), "+f"(c[2]), "+f"(c[3])
        : "r"(a[0]), "r"(a[1]), "r"(a[2]), "r"(a[3]), "r"(b[0]), "r"(b[1]));
}
#define LDSM4(d, addr) \
    asm volatile("ldmatrix.sync.aligned.m8n8.x4.shared.b16 {%0,%1,%2,%3}, [%4];" \
        : "=r"((d)[0]), "=r"((d)[1]), "=r"((d)[2]), "=r"((d)[3]) : "r"(addr))
__device__ __forceinline__ unsigned sm_u32(const void* p) {
    return (unsigned)__cvta_generic_to_shared(p);
}
__device__ __forceinline__ void cp16(void* smem, const void* gp) {
    unsigned s = sm_u32(smem);
    asm volatile("cp.async.cg.shared.global [%0], [%1], 16;\n" :: "r"(s), "l"(gp));
}
__device__ __forceinline__ void cp_commit() { asm volatile("cp.async.commit_group;\n"); }
__device__ __forceinline__ void cp_wait0() { asm volatile("cp.async.wait_group 0;\n"); }

// ---------------- 0a. RoPE table: invf[i] = 1/(i + 1985^(i/63)) ----------------
__global__ void rope_table_kernel() {
    int i = threadIdx.x;
    double lg63 = log(1985.0) / 63.0;
    double geom = exp((double)i * lg63);
    g_invf[i] = (float)(1.0 / ((double)i + geom));
}

// ---------------- 0b. tiled transpose + tf32 round ----------------
__global__ void transpose_tf32(const float* __restrict__ src, float* __restrict__ dst,
                               int R, int Cc) {   // src [R][Cc], dst [Cc][R]
    __shared__ float tile[32][33];
    int x = blockIdx.x*32 + threadIdx.x;
    int y0 = blockIdx.y*32;
    #pragma unroll
    for (int j = threadIdx.y; j < 32; j += 8)
        tile[j][threadIdx.x] = src[(size_t)(y0+j)*Cc + x];
    __syncthreads();
    int xo = blockIdx.y*32 + threadIdx.x;
    int yo0 = blockIdx.x*32;
    #pragma unroll
    for (int j = threadIdx.y; j < 32; j += 8)
        dst[(size_t)(yo0+j)*R + xo] = f2tff(tile[threadIdx.x][j]);
}

// ---------------- 1. rms_bn1 (tf32-rounded output) ----------------
__global__ void rmsbn1_kernel(const float* __restrict__ x, const float* __restrict__ g,
                              const float* __restrict__ ms) {
    int idx = (blockIdx.x * blockDim.x + threadIdx.x) * 4;
    if (idx >= B_*S_*C_) return;
    float4 xv = *(const float4*)(x + idx);
    int c = idx % C_;
    float4 o;
    o.x = f2tff(xv.x * g[c+0] * rsqrtf(ms[c+0] + EPSF));
    o.y = f2tff(xv.y * g[c+1] * rsqrtf(ms[c+1] + EPSF));
    o.z = f2tff(xv.z * g[c+2] * rsqrtf(ms[c+2] + EPSF));
    o.w = f2tff(xv.w * g[c+3] * rsqrtf(ms[c+3] + EPSF));
    *(float4*)(g_h + idx) = o;
}

// ---------------- 2. tf32 GEMM 128x128x32, ldmatrix feeds, B transposed [N][K] ----
#define AS_STR 36
#define BS_STR 36
#define AS_BUF (128*AS_STR)
#define BS_BUF (128*BS_STR)

template<int MODE>
__global__ void __launch_bounds__(256, 2) tf32gemm_kernel(
    const float* __restrict__ A, const float* __restrict__ Bt, float* __restrict__ Cm,
    int M, int N, int K,
    const float* __restrict__ bias, const float* __restrict__ bng,
    const float* __restrict__ bnms,
    float* __restrict__ gq, float* __restrict__ gk, float* __restrict__ gv)
{
    extern __shared__ float sm[];
    float* As = sm;
    float* Bs = sm + 2*AS_BUF;

    int tid = threadIdx.x;
    int lane = tid & 31, wid = tid >> 5;
    int wm = wid & 3, wn = wid >> 2;
    int g = lane >> 2, q = lane & 3;
    int bx = blockIdx.x, by = blockIdx.y;

    int t7 = lane & 7, qb0 = (lane >> 3) & 1, qb1 = (lane >> 4) & 1;
    unsigned aoff[2], boff[4];
    #pragma unroll
    for (int mt = 0; mt < 2; mt++)
        aoff[mt] = ((wm*32 + mt*16 + qb0*8 + t7)*AS_STR + qb1*4)*4;
    #pragma unroll
    for (int nt2 = 0; nt2 < 4; nt2++)
        boff[nt2] = ((wn*64 + nt2*16 + qb1*8 + t7)*BS_STR + qb0*4)*4;

    float acc[2][8][4];
    #pragma unroll
    for (int mt = 0; mt < 2; mt++)
        #pragma unroll
        for (int nt = 0; nt < 8; nt++)
            #pragma unroll
            for (int i = 0; i < 4; i++) acc[mt][nt][i] = 0.f;

    const int nk = K / 32;
    {
        #pragma unroll
        for (int i = 0; i < 4; i++) {
            int f4 = tid + i*256;
            int r = f4 >> 3, c = (f4 & 7) * 4;
            cp16(As + r*AS_STR + c, A + (size_t)(by*128 + r)*K + c);
            cp16(Bs + r*BS_STR + c, Bt + (size_t)(bx*128 + r)*K + c);
        }
        cp_commit();
    }

    for (int kt = 0; kt < nk; kt++) {
        cp_wait0();
        __syncthreads();
        if (kt + 1 < nk) {
            float* Ad = As + ((kt+1)&1)*AS_BUF;
            float* Bd = Bs + ((kt+1)&1)*BS_BUF;
            int k0 = (kt+1)*32;
            #pragma unroll
            for (int i = 0; i < 4; i++) {
                int f4 = tid + i*256;
                int r = f4 >> 3, c = (f4 & 7) * 4;
                cp16(Ad + r*AS_STR + c, A + (size_t)(by*128 + r)*K + k0 + c);
                cp16(Bd + r*BS_STR + c, Bt + (size_t)(bx*128 + r)*K + k0 + c);
            }
            cp_commit();
        }
        unsigned uA = sm_u32(As + (kt&1)*AS_BUF);
        unsigned uB = sm_u32(Bs + (kt&1)*BS_BUF);
        #pragma unroll
        for (int kk = 0; kk < 32; kk += 8) {
            unsigned a[2][4], b[4][4];
            LDSM4(a[0], uA + aoff[0] + kk*4);
            LDSM4(a[1], uA + aoff[1] + kk*4);
            #pragma unroll
            for (int nt2 = 0; nt2 < 4; nt2++) LDSM4(b[nt2], uB + boff[nt2] + kk*4);
            #pragma unroll
            for (int mt = 0; mt < 2; mt++)
                #pragma unroll
                for (int nt = 0; nt < 8; nt++)
                    mma_tf32(acc[mt][nt], a[mt], &b[nt>>1][(nt&1)*2]);
        }
    }

    #pragma unroll
    for (int mt = 0; mt < 2; mt++) {
        int row = by*128 + wm*32 + mt*16 + g;
        #pragma unroll
        for (int nt = 0; nt < 8; nt++) {
            int col = bx*128 + wn*64 + nt*8 + 2*q;
            float v0 = acc[mt][nt][0], v1 = acc[mt][nt][1];
            float v2 = acc[mt][nt][2], v3 = acc[mt][nt][3];
            if (MODE == 2) {
                float s0 = bng[col]   * rsqrtf(bnms[col]   + EPSF);
                float s1 = bng[col+1] * rsqrtf(bnms[col+1] + EPSF);
                v0 = (v0 + bias[col])   * s0;
                v1 = (v1 + bias[col+1]) * s1;
                v2 = (v2 + bias[col])   * s0;
                v3 = (v3 + bias[col+1]) * s1;
                *(float2*)(Cm + (size_t)row*N + col)     = make_float2(v0, v1);
                *(float2*)(Cm + (size_t)(row+8)*N + col) = make_float2(v2, v3);
            } else {
                float *d0, *d1;
                if (col < 2048) {
                    d0 = gq + (size_t)row*2048 + col;
                    d1 = gq + (size_t)(row+8)*2048 + col;
                } else if (col < 2560) {
                    d0 = gk + (size_t)row*512 + (col - 2048);
                    d1 = gk + (size_t)(row+8)*512 + (col - 2048);
                } else {
                    d0 = gv + (size_t)row*384 + (col - 2560);
                    d1 = gv + (size_t)(row+8)*384 + (col - 2560);
                }
                *(float2*)d0 = make_float2(v0, v1);
                *(float2*)d1 = make_float2(v2, v3);
            }
        }
    }
}

// ---------------- 3. per-head LayerNorm (+RoPE via table) ----------------
// OUT: 0 = in-place (k), 1 = in-place with Q-prescale, 2 = transposed V write
template<int D, bool ROPE, int H, int OUT>
__global__ void ln_head_kernel(float* __restrict__ data, const float* __restrict__ gg,
                               const float* __restrict__ bb, float* __restrict__ vt) {
    const int NV = D / 32;
    int gw = (blockIdx.x * blockDim.x + threadIdx.x) >> 5;
    int lane = threadIdx.x & 31;
    float* row = data + (size_t)gw * D;
    int s = (gw / H) % S_;
    int d0 = lane * NV;

    float vals[NV];
    #pragma unroll
    for (int i = 0; i < NV; i++) vals[i] = row[d0 + i];

    float sum = 0.f, sq = 0.f;
    #pragma unroll
    for (int i = 0; i < NV; i++) { sum += vals[i]; sq += vals[i]*vals[i]; }
    #pragma unroll
    for (int off = 16; off > 0; off >>= 1) {
        sum += __shfl_xor_sync(0xffffffffu, sum, off);
        sq  += __shfl_xor_sync(0xffffffffu, sq,  off);
    }
    float mean = sum * (1.0f / D);
    float var  = sq  * (1.0f / D) - mean * mean;
    float inv  = rsqrtf(var + EPSF);
    #pragma unroll
    for (int i = 0; i < NV; i++)
        vals[i] = (vals[i] - mean) * inv * gg[d0 + i] + bb[d0 + i];

    if (ROPE) {
        #pragma unroll
        for (int p = 0; p < NV/2; p++) {
            int fi = (d0 >> 1) + p;
            float invf = g_invf[fi];
            float theta = (float)s * invf;
            float sn, cs;
            sincosf(theta, &sn, &cs);
            float x0 = vals[2*p], x1 = vals[2*p + 1];
            vals[2*p]     = x0 * cs - x1 * sn;
            vals[2*p + 1] = x1 * cs + x0 * sn;
        }
    }
    if (OUT == 1) {
        // fold tanh-softmax front-end into Q: (1/sqrt(128)) * (1/5)
        const float QPRE = 0.2f * 0.08838834764831845f;
        #pragma unroll
        for (int i = 0; i < NV; i++) row[d0 + i] = f2tff(vals[i] * QPRE);
    } else if (OUT == 2) {
        int kv = gw % H;
        int b  = gw / (H * S_);
        float* base = vt + ((size_t)(b*H + kv)*D)*S_ + s;
        #pragma unroll
        for (int i = 0; i < NV; i++) base[(size_t)(d0 + i)*S_] = f2tff(vals[i]);
    } else {
        #pragma unroll
        for (int i = 0; i < NV; i++) row[d0 + i] = f2tff(vals[i]);
    }
}

// ---------------- 4. GQA flash: warp-private keys + register pipelining ---------
// 64 rows (2 heads x 32 q) x 32-key tiles; 8 warps (4m x 2n); warp owns 16 keys,
// partial O merged once at the end. 2 CTAs/SM. tanh.approx softmax.
#define QS_STR 132
#define VT_STR 36
#define PS_STR 36
#define MG_STR 100
#define FQ_OFF 0
#define FK_OFF (64*QS_STR)              // 8448
#define FK_BUF (32*QS_STR)              // 4224
#define FV_OFF (FK_OFF + 2*FK_BUF)      // 16896
#define FV_BUF (96*VT_STR)              // 3456
#define FP_OFF (FV_OFF + 2*FV_BUF)      // 23808
#define FR_OFF (FP_OFF + 64*PS_STR)     // 26112
#define FLASH_SMEM ((FR_OFF + 128) * 4) // 104960 B

__global__ void __launch_bounds__(256, 2) flash_kernel() {
    extern __shared__ float sm[];
    float* Qs = sm + FQ_OFF;
    float* Ks = sm + FK_OFF;
    float* Vs = sm + FV_OFF;
    float* Ps = sm + FP_OFF;
    float* Red = sm + FR_OFF;

    int bx = blockIdx.x;                   // b*8 + kv*2 + hp
    int b  = bx >> 3;
    int kv = (bx >> 1) & 3;
    int hp = bx & 1;
    int s0 = blockIdx.y * 32;
    int tid = threadIdx.x;
    int lane = tid & 31, wid = tid >> 5;
    int wm = wid & 3, wn = wid >> 2;       // warp: 16 rows x 16 keys (private)
    int g = lane >> 2, q = lane & 3;
    int t7 = lane & 7, qb0 = (lane >> 3) & 1, qb1 = (lane >> 4) & 1;

    unsigned qoff = ((wm*16 + qb0*8 + t7)*QS_STR + qb1*4)*4;
    unsigned koff = ((wn*16 + qb1*8 + t7)*QS_STR + qb0*4)*4;
    unsigned poff = ((wm*16 + qb0*8 + t7)*PS_STR + wn*16 + qb1*4)*4;
    unsigned voff[6];
    #pragma unroll
    for (int nt = 0; nt < 6; nt++)
        voff[nt] = ((nt*16 + qb1*8 + t7)*VT_STR + wn*16 + qb0*4)*4;
    unsigned uQ = sm_u32(Qs) + qoff;
    unsigned uP = sm_u32(Ps) + poff;

    float acc[12][4];                      // 16 rows x 96 dv partial (own keys)
    #pragma unroll
    for (int m = 0; m < 12; m++)
        #pragma unroll
        for (int i = 0; i < 4; i++) acc[m][i] = 0.f;
    float rs[2] = {0.f, 0.f};

    const float* vtb = g_vt + ((size_t)(b*HKV_ + kv)*DV_)*S_;

    // prefetch Q (64 rows = 2 heads x 32 queries) + KV tile 0
    {
        #pragma unroll
        for (int i = 0; i < 8; i++) {
            int f4 = tid + i*256;
            int r = f4 >> 5, c = (f4 & 31) * 4;
            int he = kv + (hp*2 + (r >> 5))*HKV_;
            int qr = r & 31;
            cp16(Qs + r*QS_STR + c,
                 g_q + ((size_t)((b*S_ + s0 + qr)*HQ_ + he))*DQK_ + c);
        }
        const float* kb = g_k + ((size_t)(b*S_)*HKV_ + kv)*DQK_;
        #pragma unroll
        for (int i = 0; i < 4; i++) {
            int f4 = tid + i*256;
            int r = f4 >> 5, c = (f4 & 31) * 4;
            cp16(Ks + r*QS_STR + c, kb + (size_t)r*HKV_*DQK_ + c);
        }
        #pragma unroll
        for (int i = 0; i < 3; i++) {
            int f4 = tid + i*256;
            int r = f4 >> 3, c = (f4 & 7) * 4;
            cp16(Vs + r*VT_STR + c, vtb + (size_t)r*S_ + c);
        }
        cp_commit();
    }

    int prow = wm*16 + g;

    for (int t0 = 0; t0 < 64; t0++) {
        cp_wait0();
        __syncthreads();                   // only block barrier in the tile
        if (t0 + 1 < 64) {
            const float* kb = g_k + ((size_t)(b*S_ + (t0+1)*32)*HKV_ + kv)*DQK_;
            float* kd = Ks + ((t0+1)&1)*FK_BUF;
            float* vd = Vs + ((t0+1)&1)*FV_BUF;
            #pragma unroll
            for (int i = 0; i < 4; i++) {
                int f4 = tid + i*256;
                int r = f4 >> 5, c = (f4 & 31) * 4;
                cp16(kd + r*QS_STR + c, kb + (size_t)r*HKV_*DQK_ + c);
            }
            #pragma unroll
            for (int i = 0; i < 3; i++) {
                int f4 = tid + i*256;
                int r = f4 >> 3, c = (f4 & 7) * 4;
                cp16(vd + r*VT_STR + c, vtb + (size_t)r*S_ + (t0+1)*32 + c);
            }
            cp_commit();
        }
        unsigned uK = sm_u32(Ks + (t0&1)*FK_BUF) + koff;
        unsigned uV = sm_u32(Vs + (t0&1)*FV_BUF);

        // S = Q K^T with register double-buffered fragments (Q pre-scaled by scl/5)
        float sacc[2][4];
        #pragma unroll
        for (int nt = 0; nt < 2; nt++)
            #pragma unroll
            for (int i = 0; i < 4; i++) sacc[nt][i] = 0.f;

        unsigned aq[2][4], bk[2][4];
        LDSM4(aq[0], uQ);
        LDSM4(bk[0], uK);
        #pragma unroll
        for (int i = 0; i < 16; i++) {
            if (i < 15) {
                LDSM4(aq[(i+1)&1], uQ + (i+1)*32);
                LDSM4(bk[(i+1)&1], uK + (i+1)*32);
            }
            mma_tf32(sacc[0], aq[i&1], &bk[i&1][0]);
            mma_tf32(sacc[1], aq[i&1], &bk[i&1][2]);
        }

        // preload V fragments (kc0) — independent of softmax; latency hidden
        unsigned bv[6][4];
        #pragma unroll
        for (int nt = 0; nt < 6; nt++) LDSM4(bv[nt], uV + voff[nt]);

        // p = exp(5*tanh(l/5)) = 2^(7.2135 * tanh.approx(sacc))
        #pragma unroll
        for (int nt = 0; nt < 2; nt++) {
            #pragma unroll
            for (int ci = 0; ci < 4; ci++) {
                float t = tanhaf(sacc[nt][ci]);
                float p = ex2f(7.213475204444817f * t);
                float pr = f2tff(p);
                rs[ci >> 1] += pr;
                int row = prow + ((ci >= 2) ? 8 : 0);
                int col = wn*16 + nt*8 + 2*q + (ci & 1);
                Ps[row*PS_STR + col] = pr;
            }
        }
        __syncwarp();

        // acc += P_own @ V_own; kc1 V fragments loaded as kc0 ones retire
        unsigned ap0[4], ap1[4];
        LDSM4(ap0, uP);
        LDSM4(ap1, uP + 32);
        #pragma unroll
        for (int nt = 0; nt < 6; nt++) {
            mma_tf32(acc[2*nt],   ap0, &bv[nt][0]);
            mma_tf32(acc[2*nt+1], ap0, &bv[nt][2]);
            LDSM4(bv[nt], uV + voff[nt] + 32);
        }
        #pragma unroll
        for (int nt = 0; nt < 6; nt++) {
            mma_tf32(acc[2*nt],   ap1, &bv[nt][0]);
            mma_tf32(acc[2*nt+1], ap1, &bv[nt][2]);
        }
    }

    // row sums: reduce over q lanes; per-wn partials to Red
    #pragma unroll
    for (int i = 0; i < 2; i++) {
        rs[i] += __shfl_xor_sync(0xffffffffu, rs[i], 1);
        rs[i] += __shfl_xor_sync(0xffffffffu, rs[i], 2);
    }
    if (q == 0) {
        Red[prow*2 + wn]     = rs[0];
        Red[(prow+8)*2 + wn] = rs[1];
    }
    __syncthreads();                       // K buffers dead; Red ready

    // merge partial O across the 2 wn warps via smem (alias of Ks)
    float* Mg = Ks;                        // [64][MG_STR]
    if (wn == 1) {
        #pragma unroll
        for (int m = 0; m < 12; m++) {
            int dv = m*8 + 2*q;
            *(float2*)&Mg[prow*MG_STR + dv]     = make_float2(acc[m][0], acc[m][1]);
            *(float2*)&Mg[(prow+8)*MG_STR + dv] = make_float2(acc[m][2], acc[m][3]);
        }
    }
    __syncthreads();
    if (wn == 0) {
        float inv0 = 1.0f / (Red[prow*2] + Red[prow*2 + 1]);
        float inv1 = 1.0f / (Red[(prow+8)*2] + Red[(prow+8)*2 + 1]);
        int r0 = prow, r1 = prow + 8;
        int he0 = kv + (hp*2 + (r0 >> 5))*HKV_;
        int he1 = kv + (hp*2 + (r1 >> 5))*HKV_;
        size_t base0 = ((size_t)((b*S_ + s0 + (r0 & 31))*HQ_ + he0))*DV_;
        size_t base1 = ((size_t)((b*S_ + s0 + (r1 & 31))*HQ_ + he1))*DV_;
        #pragma unroll
        for (int m = 0; m < 12; m++) {
            int dv = m*8 + 2*q;
            float2 o0 = *(float2*)&Mg[prow*MG_STR + dv];
            float2 o1 = *(float2*)&Mg[(prow+8)*MG_STR + dv];
            *(float2*)(g_y + base0 + dv) =
                make_float2(f2tff((acc[m][0] + o0.x)*inv0), f2tff((acc[m][1] + o0.y)*inv0));
            *(float2*)(g_y + base1 + dv) =
                make_float2(f2tff((acc[m][2] + o1.x)*inv1), f2tff((acc[m][3] + o1.y)*inv1));
        }
    }
}

// ---------------- launch ----------------
extern "C" void kernel_launch(void* const* d_in, const int* in_sizes, int n_in,
                              void* d_out, int out_size) {
    const float* x      = (const float*)d_in[0];
    const float* bn1_g  = (const float*)d_in[1];
    const float* bn1_ms = (const float*)d_in[2];
    const float* Wq     = (const float*)d_in[3];
    const float* Wk     = (const float*)d_in[4];
    const float* Wv     = (const float*)d_in[5];
    const float* qn_g   = (const float*)d_in[6];
    const float* qn_b   = (const float*)d_in[7];
    const float* kn_g   = (const float*)d_in[8];
    const float* kn_b   = (const float*)d_in[9];
    const float* vn_g   = (const float*)d_in[10];
    const float* vn_b   = (const float*)d_in[11];
    const float* Wo     = (const float*)d_in[12];
    const float* bo     = (const float*)d_in[13];
    const float* bn2_g  = (const float*)d_in[14];
    const float* bn2_ms = (const float*)d_in[15];
    float* out = (float*)d_out;

    float *ph, *pq, *pk, *pv, *pvt, *py, *pwqkv, *pwo;
    cudaGetSymbolAddress((void**)&ph, g_h);
    cudaGetSymbolAddress((void**)&pq, g_q);
    cudaGetSymbolAddress((void**)&pk, g_k);
    cudaGetSymbolAddress((void**)&pv, g_v);
    cudaGetSymbolAddress((void**)&pvt, g_vt);
    cudaGetSymbolAddress((void**)&py, g_y);
    cudaGetSymbolAddress((void**)&pwqkv, g_wqkv);
    cudaGetSymbolAddress((void**)&pwo, g_wo);

    const int M = B_ * S_;
    const int gemm_smem = (2*AS_BUF + 2*BS_BUF) * 4;

    cudaFuncSetAttribute(tf32gemm_kernel<1>, cudaFuncAttributeMaxDynamicSharedMemorySize, gemm_smem);
    cudaFuncSetAttribute(tf32gemm_kernel<2>, cudaFuncAttributeMaxDynamicSharedMemorySize, gemm_smem);
    cudaFuncSetAttribute(flash_kernel, cudaFuncAttributeMaxDynamicSharedMemorySize, FLASH_SMEM);

    // 0. RoPE table + weight transpose/tf32 conversion
    rope_table_kernel<<<1, 64>>>();
    {
        dim3 blk(32, 8);
        transpose_tf32<<<dim3(2048/32, C_/32), blk>>>(Wq, pwqkv,           C_, 2048);
        transpose_tf32<<<dim3(512/32,  C_/32), blk>>>(Wk, pwqkv + 2048*C_, C_, 512);
        transpose_tf32<<<dim3(384/32,  C_/32), blk>>>(Wv, pwqkv + 2560*C_, C_, 384);
        transpose_tf32<<<dim3(C_/32,   C_/32), blk>>>(Wo, pwo,             C_, C_);
    }

    // 1. rms_bn1
    rmsbn1_kernel<<<(B_*S_*C_/4 + 255)/256, 256>>>(x, bn1_g, bn1_ms);

    // 2. fused QKV projection
    tf32gemm_kernel<1><<<dim3(NQKV/128, M/128), 256, gemm_smem>>>(
        ph, pwqkv, nullptr, M, NQKV, C_, nullptr, nullptr, nullptr, pq, pk, pv);

    // 3. per-head LN (+RoPE); Q pre-scaled for tanh softmax; V transposed
    ln_head_kernel<DQK_, true,  HQ_,  1><<<(B_*S_*HQ_)/8,  256>>>(pq, qn_g, qn_b, nullptr);
    ln_head_kernel<DQK_, true,  HKV_, 0><<<(B_*S_*HKV_)/8, 256>>>(pk, kn_g, kn_b, nullptr);
    ln_head_kernel<DV_,  false, HKV_, 2><<<(B_*S_*HKV_)/8, 256>>>(pv, vn_g, vn_b, pvt);

    // 4. attention (GQA pair per CTA; warp-private keys; 2 CTAs/SM; tanh.approx)
    flash_kernel<<<dim3(B_*HKV_*2, S_/32), 256, FLASH_SMEM>>>();

    // 5. output projection + bias + rms_bn2
    tf32gemm_kernel<2><<<dim3(C_/128, M/128), 256, gemm_smem>>>(
        py, pwo, out, M, C_, HQ_*DV_, bo, bn2_g, bn2_ms, nullptr, nullptr, nullptr);
}

// round 13
// speedup vs baseline: 1.1050x; 1.0501x over previous
#include <cuda_runtime.h>
#include <math.h>

#define B_ 2
#define S_ 2048
#define C_ 1536
#define HQ_ 16
#define HKV_ 4
#define DQK_ 128
#define DV_ 96
#define EPSF 1e-5f
#define NQKV 2944   // 2048 + 512 + 384

// ---------------- scratch ----------------
__device__ float g_h[B_*S_*C_];
__device__ float g_q[B_*S_*HQ_*DQK_];
__device__ float g_k[B_*S_*HKV_*DQK_];
__device__ float g_v[B_*S_*HKV_*DV_];
__device__ float g_vt[B_*HKV_*DV_*S_];  // V transposed [b][kv][dv][s]
__device__ float g_y[B_*S_*HQ_*DV_];
__device__ float g_wqkv[NQKV*C_];       // tf32 Wq|Wk|Wv, TRANSPOSED [N][K]
__device__ float g_wo[C_*C_];           // tf32 Wo, TRANSPOSED [N][K]
__device__ float g_invf[64];            // RoPE inverse frequencies

// ---------------- helpers ----------------
__device__ __forceinline__ unsigned f2tf(float f) {
    unsigned u;
    asm("cvt.rna.tf32.f32 %0, %1;" : "=r"(u) : "f"(f));
    return u;
}
__device__ __forceinline__ float f2tff(float f) { return __uint_as_float(f2tf(f)); }
__device__ __forceinline__ float ex2f(float x) {
    float r;
    asm("ex2.approx.ftz.f32 %0, %1;" : "=f"(r) : "f"(x));
    return r;
}
__device__ __forceinline__ float tanhaf(float x) {
    float r;
    asm("tanh.approx.f32 %0, %1;" : "=f"(r) : "f"(x));
    return r;
}
__device__ __forceinline__ void mma_tf32(float c[4], const unsigned a[4], const unsigned b[2]) {
    asm volatile(
        "mma.sync.aligned.m16n8k8.row.col.f32.tf32.tf32.f32 "
        "{%0,%1,%2,%3},{%4,%5,%6,%7},{%8,%9},{%0,%1,%2,%3};"
        : "+f"(c[0]), "+f"(c[1]), "+f"(c[2]), "+f"(c[3])
        : "r"(a[0]), "r"(a[1]), "r"(a[2]), "r"(a[3]), "r"(b[0]), "r"(b[1]));
}
#define LDSM4(d, addr) \
    asm volatile("ldmatrix.sync.aligned.m8n8.x4.shared.b16 {%0,%1,%2,%3}, [%4];" \
        : "=r"((d)[0]), "=r"((d)[1]), "=r"((d)[2]), "=r"((d)[3]) : "r"(addr))
__device__ __forceinline__ unsigned sm_u32(const void* p) {
    return (unsigned)__cvta_generic_to_shared(p);
}
__device__ __forceinline__ void cp16(void* smem, const void* gp) {
    unsigned s = sm_u32(smem);
    asm volatile("cp.async.cg.shared.global [%0], [%1], 16;\n" :: "r"(s), "l"(gp));
}
__device__ __forceinline__ void cp_commit() { asm volatile("cp.async.commit_group;\n"); }
__device__ __forceinline__ void cp_wait0() { asm volatile("cp.async.wait_group 0;\n"); }

// ---------------- 0a. RoPE table: invf[i] = 1/(i + 1985^(i/63)) ----------------
__global__ void rope_table_kernel() {
    int i = threadIdx.x;
    double lg63 = log(1985.0) / 63.0;
    double geom = exp((double)i * lg63);
    g_invf[i] = (float)(1.0 / ((double)i + geom));
}

// ---------------- 0b. tiled transpose + tf32 round ----------------
__global__ void transpose_tf32(const float* __restrict__ src, float* __restrict__ dst,
                               int R, int Cc) {   // src [R][Cc], dst [Cc][R]
    __shared__ float tile[32][33];
    int x = blockIdx.x*32 + threadIdx.x;
    int y0 = blockIdx.y*32;
    #pragma unroll
    for (int j = threadIdx.y; j < 32; j += 8)
        tile[j][threadIdx.x] = src[(size_t)(y0+j)*Cc + x];
    __syncthreads();
    int xo = blockIdx.y*32 + threadIdx.x;
    int yo0 = blockIdx.x*32;
    #pragma unroll
    for (int j = threadIdx.y; j < 32; j += 8)
        dst[(size_t)(yo0+j)*R + xo] = f2tff(tile[threadIdx.x][j]);
}

// ---------------- 1. rms_bn1 (tf32-rounded output) ----------------
__global__ void rmsbn1_kernel(const float* __restrict__ x, const float* __restrict__ g,
                              const float* __restrict__ ms) {
    int idx = (blockIdx.x * blockDim.x + threadIdx.x) * 4;
    if (idx >= B_*S_*C_) return;
    float4 xv = *(const float4*)(x + idx);
    int c = idx % C_;
    float4 o;
    o.x = f2tff(xv.x * g[c+0] * rsqrtf(ms[c+0] + EPSF));
    o.y = f2tff(xv.y * g[c+1] * rsqrtf(ms[c+1] + EPSF));
    o.z = f2tff(xv.z * g[c+2] * rsqrtf(ms[c+2] + EPSF));
    o.w = f2tff(xv.w * g[c+3] * rsqrtf(ms[c+3] + EPSF));
    *(float4*)(g_h + idx) = o;
}

// ---------------- 2. tf32 GEMM 128x128x32, ldmatrix feeds, B transposed [N][K] ----
#define AS_STR 36
#define BS_STR 36
#define AS_BUF (128*AS_STR)
#define BS_BUF (128*BS_STR)

template<int MODE>
__global__ void __launch_bounds__(256, 2) tf32gemm_kernel(
    const float* __restrict__ A, const float* __restrict__ Bt, float* __restrict__ Cm,
    int M, int N, int K,
    const float* __restrict__ bias, const float* __restrict__ bng,
    const float* __restrict__ bnms,
    float* __restrict__ gq, float* __restrict__ gk, float* __restrict__ gv)
{
    extern __shared__ float sm[];
    float* As = sm;
    float* Bs = sm + 2*AS_BUF;

    int tid = threadIdx.x;
    int lane = tid & 31, wid = tid >> 5;
    int wm = wid & 3, wn = wid >> 2;
    int g = lane >> 2, q = lane & 3;
    int bx = blockIdx.x, by = blockIdx.y;

    int t7 = lane & 7, qb0 = (lane >> 3) & 1, qb1 = (lane >> 4) & 1;
    unsigned aoff[2], boff[4];
    #pragma unroll
    for (int mt = 0; mt < 2; mt++)
        aoff[mt] = ((wm*32 + mt*16 + qb0*8 + t7)*AS_STR + qb1*4)*4;
    #pragma unroll
    for (int nt2 = 0; nt2 < 4; nt2++)
        boff[nt2] = ((wn*64 + nt2*16 + qb1*8 + t7)*BS_STR + qb0*4)*4;

    float acc[2][8][4];
    #pragma unroll
    for (int mt = 0; mt < 2; mt++)
        #pragma unroll
        for (int nt = 0; nt < 8; nt++)
            #pragma unroll
            for (int i = 0; i < 4; i++) acc[mt][nt][i] = 0.f;

    const int nk = K / 32;
    {
        #pragma unroll
        for (int i = 0; i < 4; i++) {
            int f4 = tid + i*256;
            int r = f4 >> 3, c = (f4 & 7) * 4;
            cp16(As + r*AS_STR + c, A + (size_t)(by*128 + r)*K + c);
            cp16(Bs + r*BS_STR + c, Bt + (size_t)(bx*128 + r)*K + c);
        }
        cp_commit();
    }

    for (int kt = 0; kt < nk; kt++) {
        cp_wait0();
        __syncthreads();
        if (kt + 1 < nk) {
            float* Ad = As + ((kt+1)&1)*AS_BUF;
            float* Bd = Bs + ((kt+1)&1)*BS_BUF;
            int k0 = (kt+1)*32;
            #pragma unroll
            for (int i = 0; i < 4; i++) {
                int f4 = tid + i*256;
                int r = f4 >> 3, c = (f4 & 7) * 4;
                cp16(Ad + r*AS_STR + c, A + (size_t)(by*128 + r)*K + k0 + c);
                cp16(Bd + r*BS_STR + c, Bt + (size_t)(bx*128 + r)*K + k0 + c);
            }
            cp_commit();
        }
        unsigned uA = sm_u32(As + (kt&1)*AS_BUF);
        unsigned uB = sm_u32(Bs + (kt&1)*BS_BUF);
        #pragma unroll
        for (int kk = 0; kk < 32; kk += 8) {
            unsigned a[2][4], b[4][4];
            LDSM4(a[0], uA + aoff[0] + kk*4);
            LDSM4(a[1], uA + aoff[1] + kk*4);
            #pragma unroll
            for (int nt2 = 0; nt2 < 4; nt2++) LDSM4(b[nt2], uB + boff[nt2] + kk*4);
            #pragma unroll
            for (int mt = 0; mt < 2; mt++)
                #pragma unroll
                for (int nt = 0; nt < 8; nt++)
                    mma_tf32(acc[mt][nt], a[mt], &b[nt>>1][(nt&1)*2]);
        }
    }

    #pragma unroll
    for (int mt = 0; mt < 2; mt++) {
        int row = by*128 + wm*32 + mt*16 + g;
        #pragma unroll
        for (int nt = 0; nt < 8; nt++) {
            int col = bx*128 + wn*64 + nt*8 + 2*q;
            float v0 = acc[mt][nt][0], v1 = acc[mt][nt][1];
            float v2 = acc[mt][nt][2], v3 = acc[mt][nt][3];
            if (MODE == 2) {
                float s0 = bng[col]   * rsqrtf(bnms[col]   + EPSF);
                float s1 = bng[col+1] * rsqrtf(bnms[col+1] + EPSF);
                v0 = (v0 + bias[col])   * s0;
                v1 = (v1 + bias[col+1]) * s1;
                v2 = (v2 + bias[col])   * s0;
                v3 = (v3 + bias[col+1]) * s1;
                *(float2*)(Cm + (size_t)row*N + col)     = make_float2(v0, v1);
                *(float2*)(Cm + (size_t)(row+8)*N + col) = make_float2(v2, v3);
            } else {
                float *d0, *d1;
                if (col < 2048) {
                    d0 = gq + (size_t)row*2048 + col;
                    d1 = gq + (size_t)(row+8)*2048 + col;
                } else if (col < 2560) {
                    d0 = gk + (size_t)row*512 + (col - 2048);
                    d1 = gk + (size_t)(row+8)*512 + (col - 2048);
                } else {
                    d0 = gv + (size_t)row*384 + (col - 2560);
                    d1 = gv + (size_t)(row+8)*384 + (col - 2560);
                }
                *(float2*)d0 = make_float2(v0, v1);
                *(float2*)d1 = make_float2(v2, v3);
            }
        }
    }
}

// ---------------- 3. per-head LayerNorm (+RoPE via table) ----------------
// OUT: 0 = in-place (k), 1 = in-place with Q-prescale, 2 = transposed V write
template<int D, bool ROPE, int H, int OUT>
__global__ void ln_head_kernel(float* __restrict__ data, const float* __restrict__ gg,
                               const float* __restrict__ bb, float* __restrict__ vt) {
    const int NV = D / 32;
    int gw = (blockIdx.x * blockDim.x + threadIdx.x) >> 5;
    int lane = threadIdx.x & 31;
    float* row = data + (size_t)gw * D;
    int s = (gw / H) % S_;
    int d0 = lane * NV;

    float vals[NV];
    #pragma unroll
    for (int i = 0; i < NV; i++) vals[i] = row[d0 + i];

    float sum = 0.f, sq = 0.f;
    #pragma unroll
    for (int i = 0; i < NV; i++) { sum += vals[i]; sq += vals[i]*vals[i]; }
    #pragma unroll
    for (int off = 16; off > 0; off >>= 1) {
        sum += __shfl_xor_sync(0xffffffffu, sum, off);
        sq  += __shfl_xor_sync(0xffffffffu, sq,  off);
    }
    float mean = sum * (1.0f / D);
    float var  = sq  * (1.0f / D) - mean * mean;
    float inv  = rsqrtf(var + EPSF);
    #pragma unroll
    for (int i = 0; i < NV; i++)
        vals[i] = (vals[i] - mean) * inv * gg[d0 + i] + bb[d0 + i];

    if (ROPE) {
        #pragma unroll
        for (int p = 0; p < NV/2; p++) {
            int fi = (d0 >> 1) + p;
            float invf = g_invf[fi];
            float theta = (float)s * invf;
            float sn, cs;
            sincosf(theta, &sn, &cs);
            float x0 = vals[2*p], x1 = vals[2*p + 1];
            vals[2*p]     = x0 * cs - x1 * sn;
            vals[2*p + 1] = x1 * cs + x0 * sn;
        }
    }
    if (OUT == 1) {
        // fold tanh-softmax front-end into Q: (1/sqrt(128)) * (1/5)
        const float QPRE = 0.2f * 0.08838834764831845f;
        #pragma unroll
        for (int i = 0; i < NV; i++) row[d0 + i] = f2tff(vals[i] * QPRE);
    } else if (OUT == 2) {
        int kv = gw % H;
        int b  = gw / (H * S_);
        float* base = vt + ((size_t)(b*H + kv)*D)*S_ + s;
        #pragma unroll
        for (int i = 0; i < NV; i++) base[(size_t)(d0 + i)*S_] = f2tff(vals[i]);
    } else {
        #pragma unroll
        for (int i = 0; i < NV; i++) row[d0 + i] = f2tff(vals[i]);
    }
}

// ---------------- 4. GQA flash: warp-private keys, Q half-resident in registers --
// 64 rows (2 heads x 32 q) x 32-key tiles; 8 warps (4m x 2n); warp owns 16 keys.
// Q k0-63 fragments live in registers across all 64 tiles (halves aq LDSM traffic,
// the dominant smem-crossbar consumer). 2 CTAs/SM.
#define QS_STR 132
#define VT_STR 36
#define PS_STR 36
#define MG_STR 100
#define FQ_OFF 0
#define FK_OFF (64*QS_STR)              // 8448
#define FK_BUF (32*QS_STR)              // 4224
#define FV_OFF (FK_OFF + 2*FK_BUF)      // 16896
#define FV_BUF (96*VT_STR)              // 3456
#define FP_OFF (FV_OFF + 2*FV_BUF)      // 23808
#define FR_OFF (FP_OFF + 64*PS_STR)     // 26112
#define FLASH_SMEM ((FR_OFF + 128) * 4) // 104960 B

__global__ void __launch_bounds__(256, 2) flash_kernel() {
    extern __shared__ float sm[];
    float* Qs = sm + FQ_OFF;
    float* Ks = sm + FK_OFF;
    float* Vs = sm + FV_OFF;
    float* Ps = sm + FP_OFF;
    float* Red = sm + FR_OFF;

    int bx = blockIdx.x;                   // b*8 + kv*2 + hp
    int b  = bx >> 3;
    int kv = (bx >> 1) & 3;
    int hp = bx & 1;
    int s0 = blockIdx.y * 32;
    int tid = threadIdx.x;
    int lane = tid & 31, wid = tid >> 5;
    int wm = wid & 3, wn = wid >> 2;       // warp: 16 rows x 16 keys (private)
    int g = lane >> 2, q = lane & 3;
    int t7 = lane & 7, qb0 = (lane >> 3) & 1, qb1 = (lane >> 4) & 1;

    unsigned qoff = ((wm*16 + qb0*8 + t7)*QS_STR + qb1*4)*4;
    unsigned koff = ((wn*16 + qb1*8 + t7)*QS_STR + qb0*4)*4;
    unsigned poff = ((wm*16 + qb0*8 + t7)*PS_STR + wn*16 + qb1*4)*4;
    unsigned vofb = ((qb1*8 + t7)*VT_STR + wn*16 + qb0*4)*4;   // + nt*16*VT_STR*4
    unsigned uQ = sm_u32(Qs) + qoff;
    unsigned uP = sm_u32(Ps) + poff;

    float acc[12][4];                      // 16 rows x 96 dv partial (own keys)
    #pragma unroll
    for (int m = 0; m < 12; m++)
        #pragma unroll
        for (int i = 0; i < 4; i++) acc[m][i] = 0.f;
    float rs[2] = {0.f, 0.f};

    const float* vtb = g_vt + ((size_t)(b*HKV_ + kv)*DV_)*S_;

    // prefetch Q (64 rows = 2 heads x 32 queries) + KV tile 0
    {
        #pragma unroll
        for (int i = 0; i < 8; i++) {
            int f4 = tid + i*256;
            int r = f4 >> 5, c = (f4 & 31) * 4;
            int he = kv + (hp*2 + (r >> 5))*HKV_;
            int qr = r & 31;
            cp16(Qs + r*QS_STR + c,
                 g_q + ((size_t)((b*S_ + s0 + qr)*HQ_ + he))*DQK_ + c);
        }
        const float* kb = g_k + ((size_t)(b*S_)*HKV_ + kv)*DQK_;
        #pragma unroll
        for (int i = 0; i < 4; i++) {
            int f4 = tid + i*256;
            int r = f4 >> 5, c = (f4 & 31) * 4;
            cp16(Ks + r*QS_STR + c, kb + (size_t)r*HKV_*DQK_ + c);
        }
        #pragma unroll
        for (int i = 0; i < 3; i++) {
            int f4 = tid + i*256;
            int r = f4 >> 3, c = (f4 & 7) * 4;
            cp16(Vs + r*VT_STR + c, vtb + (size_t)r*S_ + c);
        }
        cp_commit();
    }

    int prow = wm*16 + g;

    // Q, K0, V0 landed; hoist Q k0-63 fragments into persistent registers
    cp_wait0();
    __syncthreads();
    unsigned aqr[8][4];
    #pragma unroll
    for (int kk = 0; kk < 8; kk++) LDSM4(aqr[kk], uQ + kk*32);

    // prefetch KV tile 1
    {
        const float* kb = g_k + ((size_t)(b*S_ + 32)*HKV_ + kv)*DQK_;
        #pragma unroll
        for (int i = 0; i < 4; i++) {
            int f4 = tid + i*256;
            int r = f4 >> 5, c = (f4 & 31) * 4;
            cp16(Ks + FK_BUF + r*QS_STR + c, kb + (size_t)r*HKV_*DQK_ + c);
        }
        #pragma unroll
        for (int i = 0; i < 3; i++) {
            int f4 = tid + i*256;
            int r = f4 >> 3, c = (f4 & 7) * 4;
            cp16(Vs + FV_BUF + r*VT_STR + c, vtb + (size_t)r*S_ + 32 + c);
        }
        cp_commit();
    }

    for (int t0 = 0; t0 < 64; t0++) {
        if (t0 > 0) {
            cp_wait0();
            __syncthreads();               // only block barrier in the tile
            if (t0 + 1 < 64) {
                const float* kb = g_k + ((size_t)(b*S_ + (t0+1)*32)*HKV_ + kv)*DQK_;
                float* kd = Ks + ((t0+1)&1)*FK_BUF;
                float* vd = Vs + ((t0+1)&1)*FV_BUF;
                #pragma unroll
                for (int i = 0; i < 4; i++) {
                    int f4 = tid + i*256;
                    int r = f4 >> 5, c = (f4 & 31) * 4;
                    cp16(kd + r*QS_STR + c, kb + (size_t)r*HKV_*DQK_ + c);
                }
                #pragma unroll
                for (int i = 0; i < 3; i++) {
                    int f4 = tid + i*256;
                    int r = f4 >> 3, c = (f4 & 7) * 4;
                    cp16(vd + r*VT_STR + c, vtb + (size_t)r*S_ + (t0+1)*32 + c);
                }
                cp_commit();
            }
        }
        unsigned uK = sm_u32(Ks + (t0&1)*FK_BUF) + koff;
        unsigned uV = sm_u32(Vs + (t0&1)*FV_BUF) + vofb;

        // S = Q K^T: k0-63 A-frags from registers, k64-127 LDSM'd; bk double-buffered
        float sacc[2][4];
        #pragma unroll
        for (int nt = 0; nt < 2; nt++)
            #pragma unroll
            for (int i = 0; i < 4; i++) sacc[nt][i] = 0.f;

        unsigned bk[2][4], aqh[2][4];
        LDSM4(bk[0], uK);
        #pragma unroll
        for (int i = 0; i < 16; i++) {
            if (i < 15) LDSM4(bk[(i+1)&1], uK + (i+1)*32);
            if (i >= 7 && i < 15) LDSM4(aqh[(i+1)&1], uQ + (i+1)*32);
            const unsigned* a = (i < 8) ? aqr[i] : aqh[i&1];
            mma_tf32(sacc[0], a, &bk[i&1][0]);
            mma_tf32(sacc[1], a, &bk[i&1][2]);
        }

        // preload V fragments (kc0) — independent of softmax; latency hidden
        unsigned bv[6][4];
        #pragma unroll
        for (int nt = 0; nt < 6; nt++) LDSM4(bv[nt], uV + nt*(16*VT_STR*4));

        // p = exp(5*tanh(l/5)) = 2^(7.2135 * tanh.approx(sacc)); float2 stores
        #pragma unroll
        for (int nt = 0; nt < 2; nt++) {
            float pr[4];
            #pragma unroll
            for (int ci = 0; ci < 4; ci++) {
                float t = tanhaf(sacc[nt][ci]);
                float p = ex2f(7.213475204444817f * t);
                pr[ci] = f2tff(p);
                rs[ci >> 1] += pr[ci];
            }
            int col = wn*16 + nt*8 + 2*q;
            *(float2*)&Ps[prow*PS_STR + col]     = make_float2(pr[0], pr[1]);
            *(float2*)&Ps[(prow+8)*PS_STR + col] = make_float2(pr[2], pr[3]);
        }
        __syncwarp();

        // acc += P_own @ V_own; kc1 V fragments loaded as kc0 ones retire
        unsigned ap0[4], ap1[4];
        LDSM4(ap0, uP);
        LDSM4(ap1, uP + 32);
        #pragma unroll
        for (int nt = 0; nt < 6; nt++) {
            mma_tf32(acc[2*nt],   ap0, &bv[nt][0]);
            mma_tf32(acc[2*nt+1], ap0, &bv[nt][2]);
            LDSM4(bv[nt], uV + nt*(16*VT_STR*4) + 32);
        }
        #pragma unroll
        for (int nt = 0; nt < 6; nt++) {
            mma_tf32(acc[2*nt],   ap1, &bv[nt][0]);
            mma_tf32(acc[2*nt+1], ap1, &bv[nt][2]);
        }
    }

    // row sums: reduce over q lanes; per-wn partials to Red
    #pragma unroll
    for (int i = 0; i < 2; i++) {
        rs[i] += __shfl_xor_sync(0xffffffffu, rs[i], 1);
        rs[i] += __shfl_xor_sync(0xffffffffu, rs[i], 2);
    }
    if (q == 0) {
        Red[prow*2 + wn]     = rs[0];
        Red[(prow+8)*2 + wn] = rs[1];
    }
    __syncthreads();                       // K buffers dead; Red ready

    // merge partial O across the 2 wn warps via smem (alias of Ks)
    float* Mg = Ks;                        // [64][MG_STR]
    if (wn == 1) {
        #pragma unroll
        for (int m = 0; m < 12; m++) {
            int dv = m*8 + 2*q;
            *(float2*)&Mg[prow*MG_STR + dv]     = make_float2(acc[m][0], acc[m][1]);
            *(float2*)&Mg[(prow+8)*MG_STR + dv] = make_float2(acc[m][2], acc[m][3]);
        }
    }
    __syncthreads();
    if (wn == 0) {
        float inv0 = 1.0f / (Red[prow*2] + Red[prow*2 + 1]);
        float inv1 = 1.0f / (Red[(prow+8)*2] + Red[(prow+8)*2 + 1]);
        int r0 = prow, r1 = prow + 8;
        int he0 = kv + (hp*2 + (r0 >> 5))*HKV_;
        int he1 = kv + (hp*2 + (r1 >> 5))*HKV_;
        size_t base0 = ((size_t)((b*S_ + s0 + (r0 & 31))*HQ_ + he0))*DV_;
        size_t base1 = ((size_t)((b*S_ + s0 + (r1 & 31))*HQ_ + he1))*DV_;
        #pragma unroll
        for (int m = 0; m < 12; m++) {
            int dv = m*8 + 2*q;
            float2 o0 = *(float2*)&Mg[prow*MG_STR + dv];
            float2 o1 = *(float2*)&Mg[(prow+8)*MG_STR + dv];
            *(float2*)(g_y + base0 + dv) =
                make_float2(f2tff((acc[m][0] + o0.x)*inv0), f2tff((acc[m][1] + o0.y)*inv0));
            *(float2*)(g_y + base1 + dv) =
                make_float2(f2tff((acc[m][2] + o1.x)*inv1), f2tff((acc[m][3] + o1.y)*inv1));
        }
    }
}

// ---------------- launch ----------------
extern "C" void kernel_launch(void* const* d_in, const int* in_sizes, int n_in,
                              void* d_out, int out_size) {
    const float* x      = (const float*)d_in[0];
    const float* bn1_g  = (const float*)d_in[1];
    const float* bn1_ms = (const float*)d_in[2];
    const float* Wq     = (const float*)d_in[3];
    const float* Wk     = (const float*)d_in[4];
    const float* Wv     = (const float*)d_in[5];
    const float* qn_g   = (const float*)d_in[6];
    const float* qn_b   = (const float*)d_in[7];
    const float* kn_g   = (const float*)d_in[8];
    const float* kn_b   = (const float*)d_in[9];
    const float* vn_g   = (const float*)d_in[10];
    const float* vn_b   = (const float*)d_in[11];
    const float* Wo     = (const float*)d_in[12];
    const float* bo     = (const float*)d_in[13];
    const float* bn2_g  = (const float*)d_in[14];
    const float* bn2_ms = (const float*)d_in[15];
    float* out = (float*)d_out;

    float *ph, *pq, *pk, *pv, *pvt, *py, *pwqkv, *pwo;
    cudaGetSymbolAddress((void**)&ph, g_h);
    cudaGetSymbolAddress((void**)&pq, g_q);
    cudaGetSymbolAddress((void**)&pk, g_k);
    cudaGetSymbolAddress((void**)&pv, g_v);
    cudaGetSymbolAddress((void**)&pvt, g_vt);
    cudaGetSymbolAddress((void**)&py, g_y);
    cudaGetSymbolAddress((void**)&pwqkv, g_wqkv);
    cudaGetSymbolAddress((void**)&pwo, g_wo);

    const int M = B_ * S_;
    const int gemm_smem = (2*AS_BUF + 2*BS_BUF) * 4;

    cudaFuncSetAttribute(tf32gemm_kernel<1>, cudaFuncAttributeMaxDynamicSharedMemorySize, gemm_smem);
    cudaFuncSetAttribute(tf32gemm_kernel<2>, cudaFuncAttributeMaxDynamicSharedMemorySize, gemm_smem);
    cudaFuncSetAttribute(flash_kernel, cudaFuncAttributeMaxDynamicSharedMemorySize, FLASH_SMEM);

    // 0. RoPE table + weight transpose/tf32 conversion
    rope_table_kernel<<<1, 64>>>();
    {
        dim3 blk(32, 8);
        transpose_tf32<<<dim3(2048/32, C_/32), blk>>>(Wq, pwqkv,           C_, 2048);
        transpose_tf32<<<dim3(512/32,  C_/32), blk>>>(Wk, pwqkv + 2048*C_, C_, 512);
        transpose_tf32<<<dim3(384/32,  C_/32), blk>>>(Wv, pwqkv + 2560*C_, C_, 384);
        transpose_tf32<<<dim3(C_/32,   C_/32), blk>>>(Wo, pwo,             C_, C_);
    }

    // 1. rms_bn1
    rmsbn1_kernel<<<(B_*S_*C_/4 + 255)/256, 256>>>(x, bn1_g, bn1_ms);

    // 2. fused QKV projection
    tf32gemm_kernel<1><<<dim3(NQKV/128, M/128), 256, gemm_smem>>>(
        ph, pwqkv, nullptr, M, NQKV, C_, nullptr, nullptr, nullptr, pq, pk, pv);

    // 3. per-head LN (+RoPE); Q pre-scaled for tanh softmax; V transposed
    ln_head_kernel<DQK_, true,  HQ_,  1><<<(B_*S_*HQ_)/8,  256>>>(pq, qn_g, qn_b, nullptr);
    ln_head_kernel<DQK_, true,  HKV_, 0><<<(B_*S_*HKV_)/8, 256>>>(pk, kn_g, kn_b, nullptr);
    ln_head_kernel<DV_,  false, HKV_, 2><<<(B_*S_*HKV_)/8, 256>>>(pv, vn_g, vn_b, pvt);

    // 4. attention (GQA pair per CTA; warp-private keys; Q half in registers)
    flash_kernel<<<dim3(B_*HKV_*2, S_/32), 256, FLASH_SMEM>>>();

    // 5. output projection + bias + rms_bn2
    tf32gemm_kernel<2><<<dim3(C_/128, M/128), 256, gemm_smem>>>(
        py, pwo, out, M, C_, HQ_*DV_, bo, bn2_g, bn2_ms, nullptr, nullptr, nullptr);
}

// round 15
// speedup vs baseline: 1.1071x; 1.0019x over previous
#include <cuda_runtime.h>
#include <math.h>

#define B_ 2
#define S_ 2048
#define C_ 1536
#define HQ_ 16
#define HKV_ 4
#define DQK_ 128
#define DV_ 96
#define EPSF 1e-5f
#define NQKV 2944   // 2048 + 512 + 384

// ---------------- scratch ----------------
__device__ float g_h[B_*S_*C_];
__device__ float g_q[B_*S_*HQ_*DQK_];
__device__ float g_k[B_*S_*HKV_*DQK_];
__device__ float g_v[B_*S_*HKV_*DV_];
__device__ float g_vt[B_*HKV_*DV_*S_];  // V transposed [b][kv][dv][s]
__device__ float g_y[B_*S_*HQ_*DV_];
__device__ float g_wqkv[NQKV*C_];       // tf32 Wq|Wk|Wv, TRANSPOSED [N][K]
__device__ float g_wo[C_*C_];           // tf32 Wo, TRANSPOSED [N][K]
__device__ float g_invf[64];            // RoPE inverse frequencies

// ---------------- helpers ----------------
__device__ __forceinline__ unsigned f2tf(float f) {
    unsigned u;
    asm("cvt.rna.tf32.f32 %0, %1;" : "=r"(u) : "f"(f));
    return u;
}
__device__ __forceinline__ float f2tff(float f) { return __uint_as_float(f2tf(f)); }
__device__ __forceinline__ float ex2f(float x) {
    float r;
    asm("ex2.approx.ftz.f32 %0, %1;" : "=f"(r) : "f"(x));
    return r;
}
__device__ __forceinline__ float tanhaf(float x) {
    float r;
    asm("tanh.approx.f32 %0, %1;" : "=f"(r) : "f"(x));
    return r;
}
__device__ __forceinline__ void mma_tf32(float c[4], const unsigned a[4], const unsigned b[2]) {
    asm volatile(
        "mma.sync.aligned.m16n8k8.row.col.f32.tf32.tf32.f32 "
        "{%0,%1,%2,%3},{%4,%5,%6,%7},{%8,%9},{%0,%1,%2,%3};"
        : "+f"(c[0]), "+f"(c[1]), "+f"(c[2]), "+f"(c[3])
        : "r"(a[0]), "r"(a[1]), "r"(a[2]), "r"(a[3]), "r"(b[0]), "r"(b[1]));
}
#define LDSM4(d, addr) \
    asm volatile("ldmatrix.sync.aligned.m8n8.x4.shared.b16 {%0,%1,%2,%3}, [%4];" \
        : "=r"((d)[0]), "=r"((d)[1]), "=r"((d)[2]), "=r"((d)[3]) : "r"(addr))
__device__ __forceinline__ unsigned sm_u32(const void* p) {
    return (unsigned)__cvta_generic_to_shared(p);
}
__device__ __forceinline__ void cp16(void* smem, const void* gp) {
    unsigned s = sm_u32(smem);
    asm volatile("cp.async.cg.shared.global [%0], [%1], 16;\n" :: "r"(s), "l"(gp));
}
__device__ __forceinline__ void cp_commit() { asm volatile("cp.async.commit_group;\n"); }
__device__ __forceinline__ void cp_wait0() { asm volatile("cp.async.wait_group 0;\n"); }

// ---------------- 0a. RoPE table: invf[i] = 1/(i + 1985^(i/63)) ----------------
__global__ void rope_table_kernel() {
    int i = threadIdx.x;
    double lg63 = log(1985.0) / 63.0;
    double geom = exp((double)i * lg63);
    g_invf[i] = (float)(1.0 / ((double)i + geom));
}

// ---------------- 0b. tiled transpose + tf32 round ----------------
__global__ void transpose_tf32(const float* __restrict__ src, float* __restrict__ dst,
                               int R, int Cc) {   // src [R][Cc], dst [Cc][R]
    __shared__ float tile[32][33];
    int x = blockIdx.x*32 + threadIdx.x;
    int y0 = blockIdx.y*32;
    #pragma unroll
    for (int j = threadIdx.y; j < 32; j += 8)
        tile[j][threadIdx.x] = src[(size_t)(y0+j)*Cc + x];
    __syncthreads();
    int xo = blockIdx.y*32 + threadIdx.x;
    int yo0 = blockIdx.x*32;
    #pragma unroll
    for (int j = threadIdx.y; j < 32; j += 8)
        dst[(size_t)(yo0+j)*R + xo] = f2tff(tile[threadIdx.x][j]);
}

// ---------------- 1. rms_bn1 (tf32-rounded output) ----------------
__global__ void rmsbn1_kernel(const float* __restrict__ x, const float* __restrict__ g,
                              const float* __restrict__ ms) {
    int idx = (blockIdx.x * blockDim.x + threadIdx.x) * 4;
    if (idx >= B_*S_*C_) return;
    float4 xv = *(const float4*)(x + idx);
    int c = idx % C_;
    float4 o;
    o.x = f2tff(xv.x * g[c+0] * rsqrtf(ms[c+0] + EPSF));
    o.y = f2tff(xv.y * g[c+1] * rsqrtf(ms[c+1] + EPSF));
    o.z = f2tff(xv.z * g[c+2] * rsqrtf(ms[c+2] + EPSF));
    o.w = f2tff(xv.w * g[c+3] * rsqrtf(ms[c+3] + EPSF));
    *(float4*)(g_h + idx) = o;
}

// ---------------- 2. tf32 GEMM 128x128x32, ldmatrix feeds, B transposed [N][K] ----
#define AS_STR 36
#define BS_STR 36
#define AS_BUF (128*AS_STR)
#define BS_BUF (128*BS_STR)

template<int MODE>
__global__ void __launch_bounds__(256, 2) tf32gemm_kernel(
    const float* __restrict__ A, const float* __restrict__ Bt, float* __restrict__ Cm,
    int M, int N, int K,
    const float* __restrict__ bias, const float* __restrict__ bng,
    const float* __restrict__ bnms,
    float* __restrict__ gq, float* __restrict__ gk, float* __restrict__ gv)
{
    extern __shared__ float sm[];
    float* As = sm;
    float* Bs = sm + 2*AS_BUF;

    int tid = threadIdx.x;
    int lane = tid & 31, wid = tid >> 5;
    int wm = wid & 3, wn = wid >> 2;
    int g = lane >> 2, q = lane & 3;
    int bx = blockIdx.x, by = blockIdx.y;

    int t7 = lane & 7, qb0 = (lane >> 3) & 1, qb1 = (lane >> 4) & 1;
    unsigned aoff[2], boff[4];
    #pragma unroll
    for (int mt = 0; mt < 2; mt++)
        aoff[mt] = ((wm*32 + mt*16 + qb0*8 + t7)*AS_STR + qb1*4)*4;
    #pragma unroll
    for (int nt2 = 0; nt2 < 4; nt2++)
        boff[nt2] = ((wn*64 + nt2*16 + qb1*8 + t7)*BS_STR + qb0*4)*4;

    float acc[2][8][4];
    #pragma unroll
    for (int mt = 0; mt < 2; mt++)
        #pragma unroll
        for (int nt = 0; nt < 8; nt++)
            #pragma unroll
            for (int i = 0; i < 4; i++) acc[mt][nt][i] = 0.f;

    const int nk = K / 32;
    {
        #pragma unroll
        for (int i = 0; i < 4; i++) {
            int f4 = tid + i*256;
            int r = f4 >> 3, c = (f4 & 7) * 4;
            cp16(As + r*AS_STR + c, A + (size_t)(by*128 + r)*K + c);
            cp16(Bs + r*BS_STR + c, Bt + (size_t)(bx*128 + r)*K + c);
        }
        cp_commit();
    }

    for (int kt = 0; kt < nk; kt++) {
        cp_wait0();
        __syncthreads();
        if (kt + 1 < nk) {
            float* Ad = As + ((kt+1)&1)*AS_BUF;
            float* Bd = Bs + ((kt+1)&1)*BS_BUF;
            int k0 = (kt+1)*32;
            #pragma unroll
            for (int i = 0; i < 4; i++) {
                int f4 = tid + i*256;
                int r = f4 >> 3, c = (f4 & 7) * 4;
                cp16(Ad + r*AS_STR + c, A + (size_t)(by*128 + r)*K + k0 + c);
                cp16(Bd + r*BS_STR + c, Bt + (size_t)(bx*128 + r)*K + k0 + c);
            }
            cp_commit();
        }
        unsigned uA = sm_u32(As + (kt&1)*AS_BUF);
        unsigned uB = sm_u32(Bs + (kt&1)*BS_BUF);
        #pragma unroll
        for (int kk = 0; kk < 32; kk += 8) {
            unsigned a[2][4], b[4][4];
            LDSM4(a[0], uA + aoff[0] + kk*4);
            LDSM4(a[1], uA + aoff[1] + kk*4);
            #pragma unroll
            for (int nt2 = 0; nt2 < 4; nt2++) LDSM4(b[nt2], uB + boff[nt2] + kk*4);
            #pragma unroll
            for (int mt = 0; mt < 2; mt++)
                #pragma unroll
                for (int nt = 0; nt < 8; nt++)
                    mma_tf32(acc[mt][nt], a[mt], &b[nt>>1][(nt&1)*2]);
        }
    }

    #pragma unroll
    for (int mt = 0; mt < 2; mt++) {
        int row = by*128 + wm*32 + mt*16 + g;
        #pragma unroll
        for (int nt = 0; nt < 8; nt++) {
            int col = bx*128 + wn*64 + nt*8 + 2*q;
            float v0 = acc[mt][nt][0], v1 = acc[mt][nt][1];
            float v2 = acc[mt][nt][2], v3 = acc[mt][nt][3];
            if (MODE == 2) {
                float s0 = bng[col]   * rsqrtf(bnms[col]   + EPSF);
                float s1 = bng[col+1] * rsqrtf(bnms[col+1] + EPSF);
                v0 = (v0 + bias[col])   * s0;
                v1 = (v1 + bias[col+1]) * s1;
                v2 = (v2 + bias[col])   * s0;
                v3 = (v3 + bias[col+1]) * s1;
                *(float2*)(Cm + (size_t)row*N + col)     = make_float2(v0, v1);
                *(float2*)(Cm + (size_t)(row+8)*N + col) = make_float2(v2, v3);
            } else {
                float *d0, *d1;
                if (col < 2048) {
                    d0 = gq + (size_t)row*2048 + col;
                    d1 = gq + (size_t)(row+8)*2048 + col;
                } else if (col < 2560) {
                    d0 = gk + (size_t)row*512 + (col - 2048);
                    d1 = gk + (size_t)(row+8)*512 + (col - 2048);
                } else {
                    d0 = gv + (size_t)row*384 + (col - 2560);
                    d1 = gv + (size_t)(row+8)*384 + (col - 2560);
                }
                *(float2*)d0 = make_float2(v0, v1);
                *(float2*)d1 = make_float2(v2, v3);
            }
        }
    }
}

// ---------------- 3. per-head LayerNorm (+RoPE via table) ----------------
// OUT: 0 = in-place (k), 1 = in-place with Q-prescale, 2 = transposed V write
template<int D, bool ROPE, int H, int OUT>
__global__ void ln_head_kernel(float* __restrict__ data, const float* __restrict__ gg,
                               const float* __restrict__ bb, float* __restrict__ vt) {
    const int NV = D / 32;
    int gw = (blockIdx.x * blockDim.x + threadIdx.x) >> 5;
    int lane = threadIdx.x & 31;
    float* row = data + (size_t)gw * D;
    int s = (gw / H) % S_;
    int d0 = lane * NV;

    float vals[NV];
    #pragma unroll
    for (int i = 0; i < NV; i++) vals[i] = row[d0 + i];

    float sum = 0.f, sq = 0.f;
    #pragma unroll
    for (int i = 0; i < NV; i++) { sum += vals[i]; sq += vals[i]*vals[i]; }
    #pragma unroll
    for (int off = 16; off > 0; off >>= 1) {
        sum += __shfl_xor_sync(0xffffffffu, sum, off);
        sq  += __shfl_xor_sync(0xffffffffu, sq,  off);
    }
    float mean = sum * (1.0f / D);
    float var  = sq  * (1.0f / D) - mean * mean;
    float inv  = rsqrtf(var + EPSF);
    #pragma unroll
    for (int i = 0; i < NV; i++)
        vals[i] = (vals[i] - mean) * inv * gg[d0 + i] + bb[d0 + i];

    if (ROPE) {
        #pragma unroll
        for (int p = 0; p < NV/2; p++) {
            int fi = (d0 >> 1) + p;
            float invf = g_invf[fi];
            float theta = (float)s * invf;
            float sn, cs;
            sincosf(theta, &sn, &cs);
            float x0 = vals[2*p], x1 = vals[2*p + 1];
            vals[2*p]     = x0 * cs - x1 * sn;
            vals[2*p + 1] = x1 * cs + x0 * sn;
        }
    }
    if (OUT == 1) {
        // fold tanh-softmax front-end into Q: (1/sqrt(128)) * (1/5)
        const float QPRE = 0.2f * 0.08838834764831845f;
        #pragma unroll
        for (int i = 0; i < NV; i++) row[d0 + i] = f2tff(vals[i] * QPRE);
    } else if (OUT == 2) {
        int kv = gw % H;
        int b  = gw / (H * S_);
        float* base = vt + ((size_t)(b*H + kv)*D)*S_ + s;
        #pragma unroll
        for (int i = 0; i < NV; i++) base[(size_t)(d0 + i)*S_] = f2tff(vals[i]);
    } else {
        #pragma unroll
        for (int i = 0; i < NV; i++) row[d0 + i] = f2tff(vals[i]);
    }
}

// ---------------- 4. GQA flash: P passed QK->PV entirely in registers ------------
// 64 rows (2 heads x 32 q) x 32-key tiles; 8 warps (4m x 2n); warp owns 16 keys.
// Q k0-63 fragments persistent in registers; PV A-fragments built from the
// softmax registers via intra-quad shuffles (no P smem buffer at all).
#define QS_STR 132
#define VT_STR 36
#define MG_STR 100
#define FQ_OFF 0
#define FK_OFF (64*QS_STR)              // 8448
#define FK_BUF (32*QS_STR)              // 4224
#define FV_OFF (FK_OFF + 2*FK_BUF)      // 16896
#define FV_BUF (96*VT_STR)              // 3456
#define FR_OFF (FV_OFF + 2*FV_BUF)      // 23808
#define FLASH_SMEM ((FR_OFF + 128) * 4) // 95744 B

__global__ void __launch_bounds__(256, 2) flash_kernel() {
    extern __shared__ float sm[];
    float* Qs = sm + FQ_OFF;
    float* Ks = sm + FK_OFF;
    float* Vs = sm + FV_OFF;
    float* Red = sm + FR_OFF;

    int bx = blockIdx.x;                   // b*8 + kv*2 + hp
    int b  = bx >> 3;
    int kv = (bx >> 1) & 3;
    int hp = bx & 1;
    int s0 = blockIdx.y * 32;
    int tid = threadIdx.x;
    int lane = tid & 31, wid = tid >> 5;
    int wm = wid & 3, wn = wid >> 2;       // warp: 16 rows x 16 keys (private)
    int g = lane >> 2, q = lane & 3;
    int t7 = lane & 7, qb0 = (lane >> 3) & 1, qb1 = (lane >> 4) & 1;

    unsigned qoff = ((wm*16 + qb0*8 + t7)*QS_STR + qb1*4)*4;
    unsigned koff = ((wn*16 + qb1*8 + t7)*QS_STR + qb0*4)*4;
    unsigned vofb = ((qb1*8 + t7)*VT_STR + wn*16 + qb0*4)*4;   // + nt*16*VT_STR*4
    unsigned uQ = sm_u32(Qs) + qoff;

    // shuffle sources for C->A fragment permutation (intra row-group quad)
    int srcA = (lane & ~3) | (q >> 1);     // provides col q  (slot q&1)
    int srcB = srcA + 2;                   // provides col q+4 (slot q&1)
    bool odd = (q & 1);

    float acc[12][4];                      // 16 rows x 96 dv partial (own keys)
    #pragma unroll
    for (int m = 0; m < 12; m++)
        #pragma unroll
        for (int i = 0; i < 4; i++) acc[m][i] = 0.f;
    float rs[2] = {0.f, 0.f};

    const float* vtb = g_vt + ((size_t)(b*HKV_ + kv)*DV_)*S_;

    // prefetch Q (64 rows = 2 heads x 32 queries) + KV tile 0
    {
        #pragma unroll
        for (int i = 0; i < 8; i++) {
            int f4 = tid + i*256;
            int r = f4 >> 5, c = (f4 & 31) * 4;
            int he = kv + (hp*2 + (r >> 5))*HKV_;
            int qr = r & 31;
            cp16(Qs + r*QS_STR + c,
                 g_q + ((size_t)((b*S_ + s0 + qr)*HQ_ + he))*DQK_ + c);
        }
        const float* kb = g_k + ((size_t)(b*S_)*HKV_ + kv)*DQK_;
        #pragma unroll
        for (int i = 0; i < 4; i++) {
            int f4 = tid + i*256;
            int r = f4 >> 5, c = (f4 & 31) * 4;
            cp16(Ks + r*QS_STR + c, kb + (size_t)r*HKV_*DQK_ + c);
        }
        #pragma unroll
        for (int i = 0; i < 3; i++) {
            int f4 = tid + i*256;
            int r = f4 >> 3, c = (f4 & 7) * 4;
            cp16(Vs + r*VT_STR + c, vtb + (size_t)r*S_ + c);
        }
        cp_commit();
    }

    int prow = wm*16 + g;

    // Q, K0, V0 landed; hoist Q k0-63 fragments into persistent registers
    cp_wait0();
    __syncthreads();
    unsigned aqr[8][4];
    #pragma unroll
    for (int kk = 0; kk < 8; kk++) LDSM4(aqr[kk], uQ + kk*32);

    // prefetch KV tile 1
    {
        const float* kb = g_k + ((size_t)(b*S_ + 32)*HKV_ + kv)*DQK_;
        #pragma unroll
        for (int i = 0; i < 4; i++) {
            int f4 = tid + i*256;
            int r = f4 >> 5, c = (f4 & 31) * 4;
            cp16(Ks + FK_BUF + r*QS_STR + c, kb + (size_t)r*HKV_*DQK_ + c);
        }
        #pragma unroll
        for (int i = 0; i < 3; i++) {
            int f4 = tid + i*256;
            int r = f4 >> 3, c = (f4 & 7) * 4;
            cp16(Vs + FV_BUF + r*VT_STR + c, vtb + (size_t)r*S_ + 32 + c);
        }
        cp_commit();
    }

    for (int t0 = 0; t0 < 64; t0++) {
        if (t0 > 0) {
            cp_wait0();
            __syncthreads();               // only block barrier in the tile
            if (t0 + 1 < 64) {
                const float* kb = g_k + ((size_t)(b*S_ + (t0+1)*32)*HKV_ + kv)*DQK_;
                float* kd = Ks + ((t0+1)&1)*FK_BUF;
                float* vd = Vs + ((t0+1)&1)*FV_BUF;
                #pragma unroll
                for (int i = 0; i < 4; i++) {
                    int f4 = tid + i*256;
                    int r = f4 >> 5, c = (f4 & 31) * 4;
                    cp16(kd + r*QS_STR + c, kb + (size_t)r*HKV_*DQK_ + c);
                }
                #pragma unroll
                for (int i = 0; i < 3; i++) {
                    int f4 = tid + i*256;
                    int r = f4 >> 3, c = (f4 & 7) * 4;
                    cp16(vd + r*VT_STR + c, vtb + (size_t)r*S_ + (t0+1)*32 + c);
                }
                cp_commit();
            }
        }
        unsigned uK = sm_u32(Ks + (t0&1)*FK_BUF) + koff;
        unsigned uV = sm_u32(Vs + (t0&1)*FV_BUF) + vofb;

        // S = Q K^T: k0-63 A-frags from registers, k64-127 LDSM'd; bk double-buffered
        float sacc[2][4];
        #pragma unroll
        for (int nt = 0; nt < 2; nt++)
            #pragma unroll
            for (int i = 0; i < 4; i++) sacc[nt][i] = 0.f;

        unsigned bk[2][4], aqh[2][4];
        LDSM4(bk[0], uK);
        #pragma unroll
        for (int i = 0; i < 16; i++) {
            if (i < 15) LDSM4(bk[(i+1)&1], uK + (i+1)*32);
            if (i >= 7 && i < 15) LDSM4(aqh[(i+1)&1], uQ + (i+1)*32);
            const unsigned* a = (i < 8) ? aqr[i] : aqh[i&1];
            mma_tf32(sacc[0], a, &bk[i&1][0]);
            mma_tf32(sacc[1], a, &bk[i&1][2]);
        }

        // preload V fragments (kc0) — independent of softmax; latency hidden
        unsigned bv[6][4];
        #pragma unroll
        for (int nt = 0; nt < 6; nt++) LDSM4(bv[nt], uV + nt*(16*VT_STR*4));

        // softmax p = 2^(7.2135 * tanh.approx(sacc)), then build PV A-frags
        // directly from registers: C frag (g holds cols 2q,2q+1) -> A frag
        // (g needs cols q, q+4) via intra-quad shuffles. Bit-identical to the
        // old STS/LDSM path (same tf32-rounded values).
        unsigned apf[2][4];
        #pragma unroll
        for (int nt = 0; nt < 2; nt++) {
            float pr[4];
            #pragma unroll
            for (int ci = 0; ci < 4; ci++) {
                float t = tanhaf(sacc[nt][ci]);
                pr[ci] = f2tff(ex2f(7.213475204444817f * t));
                rs[ci >> 1] += pr[ci];
            }
            float pA0 = __shfl_sync(0xffffffffu, pr[0], srcA);
            float pA1 = __shfl_sync(0xffffffffu, pr[1], srcA);
            float pA2 = __shfl_sync(0xffffffffu, pr[2], srcA);
            float pA3 = __shfl_sync(0xffffffffu, pr[3], srcA);
            float pB0 = __shfl_sync(0xffffffffu, pr[0], srcB);
            float pB1 = __shfl_sync(0xffffffffu, pr[1], srcB);
            float pB2 = __shfl_sync(0xffffffffu, pr[2], srcB);
            float pB3 = __shfl_sync(0xffffffffu, pr[3], srcB);
            apf[nt][0] = __float_as_uint(odd ? pA1 : pA0);   // P[g][q]
            apf[nt][1] = __float_as_uint(odd ? pA3 : pA2);   // P[g+8][q]
            apf[nt][2] = __float_as_uint(odd ? pB1 : pB0);   // P[g][q+4]
            apf[nt][3] = __float_as_uint(odd ? pB3 : pB2);   // P[g+8][q+4]
        }

        // acc += P_own @ V_own; kc1 V fragments loaded as kc0 ones retire
        #pragma unroll
        for (int nt = 0; nt < 6; nt++) {
            mma_tf32(acc[2*nt],   apf[0], &bv[nt][0]);
            mma_tf32(acc[2*nt+1], apf[0], &bv[nt][2]);
            LDSM4(bv[nt], uV + nt*(16*VT_STR*4) + 32);
        }
        #pragma unroll
        for (int nt = 0; nt < 6; nt++) {
            mma_tf32(acc[2*nt],   apf[1], &bv[nt][0]);
            mma_tf32(acc[2*nt+1], apf[1], &bv[nt][2]);
        }
    }

    // row sums: reduce over q lanes; per-wn partials to Red
    #pragma unroll
    for (int i = 0; i < 2; i++) {
        rs[i] += __shfl_xor_sync(0xffffffffu, rs[i], 1);
        rs[i] += __shfl_xor_sync(0xffffffffu, rs[i], 2);
    }
    if (q == 0) {
        Red[prow*2 + wn]     = rs[0];
        Red[(prow+8)*2 + wn] = rs[1];
    }
    __syncthreads();                       // K buffers dead; Red ready

    // merge partial O across the 2 wn warps via smem (alias of Ks)
    float* Mg = Ks;                        // [64][MG_STR]
    if (wn == 1) {
        #pragma unroll
        for (int m = 0; m < 12; m++) {
            int dv = m*8 + 2*q;
            *(float2*)&Mg[prow*MG_STR + dv]     = make_float2(acc[m][0], acc[m][1]);
            *(float2*)&Mg[(prow+8)*MG_STR + dv] = make_float2(acc[m][2], acc[m][3]);
        }
    }
    __syncthreads();
    if (wn == 0) {
        float inv0 = 1.0f / (Red[prow*2] + Red[prow*2 + 1]);
        float inv1 = 1.0f / (Red[(prow+8)*2] + Red[(prow+8)*2 + 1]);
        int r0 = prow, r1 = prow + 8;
        int he0 = kv + (hp*2 + (r0 >> 5))*HKV_;
        int he1 = kv + (hp*2 + (r1 >> 5))*HKV_;
        size_t base0 = ((size_t)((b*S_ + s0 + (r0 & 31))*HQ_ + he0))*DV_;
        size_t base1 = ((size_t)((b*S_ + s0 + (r1 & 31))*HQ_ + he1))*DV_;
        #pragma unroll
        for (int m = 0; m < 12; m++) {
            int dv = m*8 + 2*q;
            float2 o0 = *(float2*)&Mg[prow*MG_STR + dv];
            float2 o1 = *(float2*)&Mg[(prow+8)*MG_STR + dv];
            *(float2*)(g_y + base0 + dv) =
                make_float2(f2tff((acc[m][0] + o0.x)*inv0), f2tff((acc[m][1] + o0.y)*inv0));
            *(float2*)(g_y + base1 + dv) =
                make_float2(f2tff((acc[m][2] + o1.x)*inv1), f2tff((acc[m][3] + o1.y)*inv1));
        }
    }
}

// ---------------- launch ----------------
extern "C" void kernel_launch(void* const* d_in, const int* in_sizes, int n_in,
                              void* d_out, int out_size) {
    const float* x      = (const float*)d_in[0];
    const float* bn1_g  = (const float*)d_in[1];
    const float* bn1_ms = (const float*)d_in[2];
    const float* Wq     = (const float*)d_in[3];
    const float* Wk     = (const float*)d_in[4];
    const float* Wv     = (const float*)d_in[5];
    const float* qn_g   = (const float*)d_in[6];
    const float* qn_b   = (const float*)d_in[7];
    const float* kn_g   = (const float*)d_in[8];
    const float* kn_b   = (const float*)d_in[9];
    const float* vn_g   = (const float*)d_in[10];
    const float* vn_b   = (const float*)d_in[11];
    const float* Wo     = (const float*)d_in[12];
    const float* bo     = (const float*)d_in[13];
    const float* bn2_g  = (const float*)d_in[14];
    const float* bn2_ms = (const float*)d_in[15];
    float* out = (float*)d_out;

    float *ph, *pq, *pk, *pv, *pvt, *py, *pwqkv, *pwo;
    cudaGetSymbolAddress((void**)&ph, g_h);
    cudaGetSymbolAddress((void**)&pq, g_q);
    cudaGetSymbolAddress((void**)&pk, g_k);
    cudaGetSymbolAddress((void**)&pv, g_v);
    cudaGetSymbolAddress((void**)&pvt, g_vt);
    cudaGetSymbolAddress((void**)&py, g_y);
    cudaGetSymbolAddress((void**)&pwqkv, g_wqkv);
    cudaGetSymbolAddress((void**)&pwo, g_wo);

    const int M = B_ * S_;
    const int gemm_smem = (2*AS_BUF + 2*BS_BUF) * 4;

    cudaFuncSetAttribute(tf32gemm_kernel<1>, cudaFuncAttributeMaxDynamicSharedMemorySize, gemm_smem);
    cudaFuncSetAttribute(tf32gemm_kernel<2>, cudaFuncAttributeMaxDynamicSharedMemorySize, gemm_smem);
    cudaFuncSetAttribute(flash_kernel, cudaFuncAttributeMaxDynamicSharedMemorySize, FLASH_SMEM);

    // 0. RoPE table + weight transpose/tf32 conversion
    rope_table_kernel<<<1, 64>>>();
    {
        dim3 blk(32, 8);
        transpose_tf32<<<dim3(2048/32, C_/32), blk>>>(Wq, pwqkv,           C_, 2048);
        transpose_tf32<<<dim3(512/32,  C_/32), blk>>>(Wk, pwqkv + 2048*C_, C_, 512);
        transpose_tf32<<<dim3(384/32,  C_/32), blk>>>(Wv, pwqkv + 2560*C_, C_, 384);
        transpose_tf32<<<dim3(C_/32,   C_/32), blk>>>(Wo, pwo,             C_, C_);
    }

    // 1. rms_bn1
    rmsbn1_kernel<<<(B_*S_*C_/4 + 255)/256, 256>>>(x, bn1_g, bn1_ms);

    // 2. fused QKV projection
    tf32gemm_kernel<1><<<dim3(NQKV/128, M/128), 256, gemm_smem>>>(
        ph, pwqkv, nullptr, M, NQKV, C_, nullptr, nullptr, nullptr, pq, pk, pv);

    // 3. per-head LN (+RoPE); Q pre-scaled for tanh softmax; V transposed
    ln_head_kernel<DQK_, true,  HQ_,  1><<<(B_*S_*HQ_)/8,  256>>>(pq, qn_g, qn_b, nullptr);
    ln_head_kernel<DQK_, true,  HKV_, 0><<<(B_*S_*HKV_)/8, 256>>>(pk, kn_g, kn_b, nullptr);
    ln_head_kernel<DV_,  false, HKV_, 2><<<(B_*S_*HKV_)/8, 256>>>(pv, vn_g, vn_b, pvt);

    // 4. attention (GQA pair per CTA; P register-resident QK->PV)
    flash_kernel<<<dim3(B_*HKV_*2, S_/32), 256, FLASH_SMEM>>>();

    // 5. output projection + bias + rms_bn2
    tf32gemm_kernel<2><<<dim3(C_/128, M/128), 256, gemm_smem>>>(
        py, pwo, out, M, C_, HQ_*DV_, bo, bn2_g, bn2_ms, nullptr, nullptr, nullptr);
}